// round 3
// baseline (speedup 1.0000x reference)
#include <cuda_runtime.h>
#include <cstdint>

#define N_NODES 100000
#define N_EDGES 3200000
#define IN_DIM  384
#define HID     128

// ---------------- scratch (device globals; no allocation allowed) ----------
__device__ int   g_cnt[N_NODES];
__device__ int   g_off[N_NODES + 1];
__device__ int   g_cur[N_NODES];
__device__ int   g_csr[N_EDGES];
__device__ float g_t  [(size_t)N_NODES * 256];  // layer1 pre-transform [xWl1|xWr1]; reused as [agg2|h1]
__device__ float g_h1 [(size_t)N_NODES * HID];
__device__ float g_h2 [(size_t)N_NODES * HID];
__device__ float g_sa [N_NODES];
__device__ float g_sb [N_NODES];
__device__ float g_W1 [IN_DIM * 256];           // [W_l1 | W_r1]  (384 x 256)
__device__ float g_W2 [256 * HID];              // [W_l2 ; W_r2]  (256 x 128)

// ---------------- small utility kernels ------------------------------------
__global__ void zero_cnt_kernel() {
    int i = blockIdx.x * blockDim.x + threadIdx.x;
    if (i < N_NODES) g_cnt[i] = 0;
}

__global__ void pack_w1_kernel(const float* __restrict__ Wl, const float* __restrict__ Wr) {
    int idx = blockIdx.x * blockDim.x + threadIdx.x;
    if (idx >= IN_DIM * 256) return;
    int k = idx >> 8;          // /256
    int j = idx & 255;
    g_W1[idx] = (j < HID) ? Wl[k * HID + j] : Wr[k * HID + (j - HID)];
}

__global__ void pack_w2_kernel(const float* __restrict__ Wl, const float* __restrict__ Wr) {
    int idx = blockIdx.x * blockDim.x + threadIdx.x;
    if (idx >= 256 * HID) return;
    int k = idx >> 7;          // /128
    int j = idx & 127;
    g_W2[idx] = (k < HID) ? Wl[k * HID + j] : Wr[(k - HID) * HID + j];
}

__global__ void hist_kernel(const int* __restrict__ dst) {
    int e = blockIdx.x * blockDim.x + threadIdx.x;
    if (e < N_EDGES) atomicAdd(&g_cnt[dst[e]], 1);
}

// single-block exclusive scan over g_cnt -> g_off, g_cur
__global__ void scan_kernel() {
    __shared__ int sh[1024];
    const int tid = threadIdx.x;
    int carry = 0;
    for (int base = 0; base < N_NODES; base += 1024) {
        int idx = base + tid;
        int v = (idx < N_NODES) ? g_cnt[idx] : 0;
        sh[tid] = v;
        __syncthreads();
        #pragma unroll
        for (int off = 1; off < 1024; off <<= 1) {
            int t = (tid >= off) ? sh[tid - off] : 0;
            __syncthreads();
            sh[tid] += t;
            __syncthreads();
        }
        int incl = sh[tid];
        if (idx < N_NODES) {
            int excl = carry + incl - v;
            g_off[idx] = excl;
            g_cur[idx] = excl;
        }
        carry += sh[1023];
        __syncthreads();
    }
    if (tid == 0) g_off[N_NODES] = carry;
}

__global__ void scatter_kernel(const int* __restrict__ src, const int* __restrict__ dst) {
    int e = blockIdx.x * blockDim.x + threadIdx.x;
    if (e >= N_EDGES) return;
    int p = atomicAdd(&g_cur[dst[e]], 1);
    g_csr[p] = src[e];
}

// ---------------- SGEMM: C[M,N] = A[M,K] @ B[K,N] (+bias) ------------------
// BM=128, BN=64, BK=16, 256 threads, 8x4 per thread. N%64==0, K%16==0 assumed.
__global__ __launch_bounds__(256) void sgemm_kernel(
    const float* __restrict__ A, const float* __restrict__ B,
    float* __restrict__ C, int M, int N, int K, const float* __restrict__ bias)
{
    __shared__ float As[16][128];
    __shared__ float Bs[16][64];
    const int tid = threadIdx.x;
    const int tx = tid & 15;   // N dir, 16 lanes * 4 cols
    const int ty = tid >> 4;   // M dir, 16 rows * 8 rows
    const int rowBase = blockIdx.y * 128;
    const int colBase = blockIdx.x * 64;

    float acc[8][4];
    #pragma unroll
    for (int i = 0; i < 8; i++)
        #pragma unroll
        for (int j = 0; j < 4; j++) acc[i][j] = 0.0f;

    for (int k0 = 0; k0 < K; k0 += 16) {
        // A tile: 128 rows x 16 cols = 512 float4 slots, 2 per thread
        #pragma unroll
        for (int i = 0; i < 2; i++) {
            int slot = tid + i * 256;
            int m = slot >> 2, kq = slot & 3;
            int grow = rowBase + m;
            float4 v = make_float4(0.f, 0.f, 0.f, 0.f);
            if (grow < M) v = *(const float4*)(A + (size_t)grow * K + k0 + kq * 4);
            As[kq * 4 + 0][m] = v.x;
            As[kq * 4 + 1][m] = v.y;
            As[kq * 4 + 2][m] = v.z;
            As[kq * 4 + 3][m] = v.w;
        }
        // B tile: 16 rows x 64 cols = 256 float4, 1 per thread
        {
            int kr = tid >> 4, nq = tid & 15;
            float4 v = *(const float4*)(B + (size_t)(k0 + kr) * N + colBase + nq * 4);
            *(float4*)&Bs[kr][nq * 4] = v;
        }
        __syncthreads();

        #pragma unroll
        for (int kk = 0; kk < 16; kk++) {
            float4 a0 = *(const float4*)&As[kk][ty * 8];
            float4 a1 = *(const float4*)&As[kk][ty * 8 + 4];
            float4 b0 = *(const float4*)&Bs[kk][tx * 4];
            float a[8] = {a0.x, a0.y, a0.z, a0.w, a1.x, a1.y, a1.z, a1.w};
            float b[4] = {b0.x, b0.y, b0.z, b0.w};
            #pragma unroll
            for (int i = 0; i < 8; i++)
                #pragma unroll
                for (int j = 0; j < 4; j++)
                    acc[i][j] = fmaf(a[i], b[j], acc[i][j]);
        }
        __syncthreads();
    }

    #pragma unroll
    for (int i = 0; i < 8; i++) {
        int grow = rowBase + ty * 8 + i;
        if (grow >= M) break;
        int gcol = colBase + tx * 4;
        float4 v = make_float4(acc[i][0], acc[i][1], acc[i][2], acc[i][3]);
        if (bias) {
            v.x += bias[gcol + 0];
            v.y += bias[gcol + 1];
            v.z += bias[gcol + 2];
            v.w += bias[gcol + 3];
        }
        *(float4*)(C + (size_t)grow * N + gcol) = v;
    }
}

// ---------------- aggregation: warp per node --------------------------------
// layer 1: h1 = relu( mean_j t[j,0:128] + b_l1 + t[i,128:256] )
__global__ __launch_bounds__(256) void agg1_kernel(const float* __restrict__ b_l1) {
    int node = (blockIdx.x * blockDim.x + threadIdx.x) >> 5;
    int lane = threadIdx.x & 31;
    if (node >= N_NODES) return;
    int s = g_off[node], e = g_off[node + 1];
    float4 a0 = make_float4(0.f, 0.f, 0.f, 0.f);
    float4 a1 = make_float4(0.f, 0.f, 0.f, 0.f);
    int i = s;
    for (; i + 3 < e; i += 4) {
        int s0 = g_csr[i], s1 = g_csr[i + 1], s2 = g_csr[i + 2], s3 = g_csr[i + 3];
        float4 v0 = *(const float4*)(g_t + (size_t)s0 * 256 + lane * 4);
        float4 v1 = *(const float4*)(g_t + (size_t)s1 * 256 + lane * 4);
        float4 v2 = *(const float4*)(g_t + (size_t)s2 * 256 + lane * 4);
        float4 v3 = *(const float4*)(g_t + (size_t)s3 * 256 + lane * 4);
        a0.x += v0.x + v1.x; a0.y += v0.y + v1.y; a0.z += v0.z + v1.z; a0.w += v0.w + v1.w;
        a1.x += v2.x + v3.x; a1.y += v2.y + v3.y; a1.z += v2.z + v3.z; a1.w += v2.w + v3.w;
    }
    for (; i < e; i++) {
        int s0 = g_csr[i];
        float4 v0 = *(const float4*)(g_t + (size_t)s0 * 256 + lane * 4);
        a0.x += v0.x; a0.y += v0.y; a0.z += v0.z; a0.w += v0.w;
    }
    float inv = 1.0f / fmaxf((float)(e - s), 1.0f);
    float4 r  = *(const float4*)(g_t + (size_t)node * 256 + 128 + lane * 4);
    float4 bb = *(const float4*)(b_l1 + lane * 4);
    float4 o;
    o.x = fmaxf((a0.x + a1.x) * inv + bb.x + r.x, 0.f);
    o.y = fmaxf((a0.y + a1.y) * inv + bb.y + r.y, 0.f);
    o.z = fmaxf((a0.z + a1.z) * inv + bb.z + r.z, 0.f);
    o.w = fmaxf((a0.w + a1.w) * inv + bb.w + r.w, 0.f);
    *(float4*)(g_h1 + (size_t)node * HID + lane * 4) = o;
}

// layer 2 aggregation: g_t[i] = [ mean_j h1[j] | h1[i] ]
__global__ __launch_bounds__(256) void agg2_kernel() {
    int node = (blockIdx.x * blockDim.x + threadIdx.x) >> 5;
    int lane = threadIdx.x & 31;
    if (node >= N_NODES) return;
    int s = g_off[node], e = g_off[node + 1];
    float4 a0 = make_float4(0.f, 0.f, 0.f, 0.f);
    float4 a1 = make_float4(0.f, 0.f, 0.f, 0.f);
    int i = s;
    for (; i + 3 < e; i += 4) {
        int s0 = g_csr[i], s1 = g_csr[i + 1], s2 = g_csr[i + 2], s3 = g_csr[i + 3];
        float4 v0 = *(const float4*)(g_h1 + (size_t)s0 * HID + lane * 4);
        float4 v1 = *(const float4*)(g_h1 + (size_t)s1 * HID + lane * 4);
        float4 v2 = *(const float4*)(g_h1 + (size_t)s2 * HID + lane * 4);
        float4 v3 = *(const float4*)(g_h1 + (size_t)s3 * HID + lane * 4);
        a0.x += v0.x + v1.x; a0.y += v0.y + v1.y; a0.z += v0.z + v1.z; a0.w += v0.w + v1.w;
        a1.x += v2.x + v3.x; a1.y += v2.y + v3.y; a1.z += v2.z + v3.z; a1.w += v2.w + v3.w;
    }
    for (; i < e; i++) {
        int s0 = g_csr[i];
        float4 v0 = *(const float4*)(g_h1 + (size_t)s0 * HID + lane * 4);
        a0.x += v0.x; a0.y += v0.y; a0.z += v0.z; a0.w += v0.w;
    }
    float inv = 1.0f / fmaxf((float)(e - s), 1.0f);
    float4 o;
    o.x = (a0.x + a1.x) * inv;
    o.y = (a0.y + a1.y) * inv;
    o.z = (a0.z + a1.z) * inv;
    o.w = (a0.w + a1.w) * inv;
    *(float4*)(g_t + (size_t)node * 256 + lane * 4) = o;
    float4 own = *(const float4*)(g_h1 + (size_t)node * HID + lane * 4);
    *(float4*)(g_t + (size_t)node * 256 + 128 + lane * 4) = own;
}

// ---------------- decoder factorization ------------------------------------
// s_a[i] = h2[i] . W_lin[0:128], s_b[i] = h2[i] . W_lin[128:256]
__global__ __launch_bounds__(256) void sab_kernel(const float* __restrict__ W_lin) {
    int node = (blockIdx.x * blockDim.x + threadIdx.x) >> 5;
    int lane = threadIdx.x & 31;
    if (node >= N_NODES) return;
    float4 h  = *(const float4*)(g_h2 + (size_t)node * HID + lane * 4);
    float4 wa = *(const float4*)(W_lin + lane * 4);
    float4 wb = *(const float4*)(W_lin + 128 + lane * 4);
    float da = h.x * wa.x + h.y * wa.y + h.z * wa.z + h.w * wa.w;
    float db = h.x * wb.x + h.y * wb.y + h.z * wb.z + h.w * wb.w;
    #pragma unroll
    for (int off = 16; off > 0; off >>= 1) {
        da += __shfl_xor_sync(0xffffffff, da, off);
        db += __shfl_xor_sync(0xffffffff, db, off);
    }
    if (lane == 0) {
        g_sa[node] = da;
        g_sb[node] = db;
    }
}

__global__ void score_kernel(const int* __restrict__ pos, const int* __restrict__ neg,
                             const float* __restrict__ b_lin, float* __restrict__ out)
{
    int idx = blockIdx.x * blockDim.x + threadIdx.x;
    if (idx >= 1000000) return;
    float b = b_lin[0];
    if (idx < 500000) {
        int s = pos[idx];
        int d = pos[500000 + idx];
        out[idx] = g_sa[s] + g_sb[d] + b;
    } else {
        int e = idx - 500000;
        int s = neg[e];
        int d = neg[500000 + e];
        out[idx] = g_sa[s] + g_sb[d] + b;
    }
}

// ---------------- launch ----------------------------------------------------
extern "C" void kernel_launch(void* const* d_in, const int* in_sizes, int n_in,
                              void* d_out, int out_size)
{
    const float* x     = (const float*)d_in[0];
    const int*   ei    = (const int*)  d_in[1];
    const int*   pos   = (const int*)  d_in[2];
    const int*   neg   = (const int*)  d_in[3];
    const float* W_l1  = (const float*)d_in[4];
    const float* b_l1  = (const float*)d_in[5];
    const float* W_r1  = (const float*)d_in[6];
    const float* W_l2  = (const float*)d_in[7];
    const float* b_l2  = (const float*)d_in[8];
    const float* W_r2  = (const float*)d_in[9];
    const float* W_lin = (const float*)d_in[10];
    const float* b_lin = (const float*)d_in[11];
    float*       out   = (float*)d_out;

    const int* e_src = ei;
    const int* e_dst = ei + N_EDGES;

    void *p_t, *p_h1, *p_h2, *p_W1, *p_W2;
    cudaGetSymbolAddress(&p_t,  g_t);
    cudaGetSymbolAddress(&p_h1, g_h1);
    cudaGetSymbolAddress(&p_h2, g_h2);
    cudaGetSymbolAddress(&p_W1, g_W1);
    cudaGetSymbolAddress(&p_W2, g_W2);

    // CSR build
    zero_cnt_kernel<<<(N_NODES + 255) / 256, 256>>>();
    hist_kernel<<<(N_EDGES + 255) / 256, 256>>>(e_dst);
    scan_kernel<<<1, 1024>>>();
    scatter_kernel<<<(N_EDGES + 255) / 256, 256>>>(e_src, e_dst);

    // pack weight blocks
    pack_w1_kernel<<<(IN_DIM * 256 + 255) / 256, 256>>>(W_l1, W_r1);
    pack_w2_kernel<<<(256 * HID + 255) / 256, 256>>>(W_l2, W_r2);

    // layer 1: t = x @ [W_l1 | W_r1]   (100000 x 384) @ (384 x 256)
    {
        dim3 grid(256 / 64, (N_NODES + 127) / 128);
        sgemm_kernel<<<grid, 256>>>(x, (const float*)p_W1, (float*)p_t,
                                    N_NODES, 256, IN_DIM, nullptr);
    }
    // h1 = relu(mean-aggregate + b + root)
    agg1_kernel<<<(N_NODES * 32 + 255) / 256, 256>>>(b_l1);

    // layer 2: build [agg2 | h1], then h2 = that @ [W_l2 ; W_r2] + b_l2
    agg2_kernel<<<(N_NODES * 32 + 255) / 256, 256>>>();
    {
        dim3 grid(HID / 64, (N_NODES + 127) / 128);
        sgemm_kernel<<<grid, 256>>>((const float*)p_t, (const float*)p_W2, (float*)p_h2,
                                    N_NODES, HID, 256, b_l2);
    }

    // decoder
    sab_kernel<<<(N_NODES * 32 + 255) / 256, 256>>>(W_lin);
    score_kernel<<<(1000000 + 255) / 256, 256>>>(pos, neg, b_lin, out);
}

// round 6
// speedup vs baseline: 1.1788x; 1.1788x over previous
#include <cuda_runtime.h>
#include <cstdint>

#define N_NODES 100000
#define N_EDGES 3200000
#define IN_DIM  384
#define HID     128

// ---------------- scratch (device globals; no allocation allowed) ----------
__device__ int   g_cnt[N_NODES];
__device__ int   g_off[N_NODES + 1];
__device__ int   g_cur[N_NODES];
__device__ int   g_csr[N_EDGES];
__device__ float g_t  [(size_t)N_NODES * 256];  // layer1 pre-transform [xWl1|xWr1]; reused as [agg2|h1]
__device__ float g_h1 [(size_t)N_NODES * HID];
__device__ float g_h2 [(size_t)N_NODES * HID];
__device__ float g_sa [N_NODES];
__device__ float g_sb [N_NODES];
__device__ float g_W1 [IN_DIM * 256];           // [W_l1 | W_r1]  (384 x 256)
__device__ float g_W2 [256 * HID];              // [W_l2 ; W_r2]  (256 x 128)

// ---------------- small utility kernels ------------------------------------
__global__ void zero_cnt_kernel() {
    int i = blockIdx.x * blockDim.x + threadIdx.x;
    if (i < N_NODES) g_cnt[i] = 0;
}

__global__ void pack_w1_kernel(const float* __restrict__ Wl, const float* __restrict__ Wr) {
    int idx = blockIdx.x * blockDim.x + threadIdx.x;
    if (idx >= IN_DIM * 256) return;
    int k = idx >> 8;          // /256
    int j = idx & 255;
    g_W1[idx] = (j < HID) ? Wl[k * HID + j] : Wr[k * HID + (j - HID)];
}

__global__ void pack_w2_kernel(const float* __restrict__ Wl, const float* __restrict__ Wr) {
    int idx = blockIdx.x * blockDim.x + threadIdx.x;
    if (idx >= 256 * HID) return;
    int k = idx >> 7;          // /128
    int j = idx & 127;
    g_W2[idx] = (k < HID) ? Wl[k * HID + j] : Wr[(k - HID) * HID + j];
}

__global__ void hist_kernel(const int* __restrict__ dst) {
    int e = blockIdx.x * blockDim.x + threadIdx.x;
    if (e < N_EDGES) atomicAdd(&g_cnt[dst[e]], 1);
}

// single-block exclusive scan over g_cnt -> g_off, g_cur
__global__ void scan_kernel() {
    __shared__ int sh[1024];
    const int tid = threadIdx.x;
    int carry = 0;
    for (int base = 0; base < N_NODES; base += 1024) {
        int idx = base + tid;
        int v = (idx < N_NODES) ? g_cnt[idx] : 0;
        sh[tid] = v;
        __syncthreads();
        #pragma unroll
        for (int off = 1; off < 1024; off <<= 1) {
            int t = (tid >= off) ? sh[tid - off] : 0;
            __syncthreads();
            sh[tid] += t;
            __syncthreads();
        }
        int incl = sh[tid];
        if (idx < N_NODES) {
            int excl = carry + incl - v;
            g_off[idx] = excl;
            g_cur[idx] = excl;
        }
        carry += sh[1023];
        __syncthreads();
    }
    if (tid == 0) g_off[N_NODES] = carry;
}

__global__ void scatter_kernel(const int* __restrict__ src, const int* __restrict__ dst) {
    int e = blockIdx.x * blockDim.x + threadIdx.x;
    if (e >= N_EDGES) return;
    int p = atomicAdd(&g_cur[dst[e]], 1);
    g_csr[p] = src[e];
}

// ---------------- 3xTF32 tensor-core GEMM (fp32 accuracy) ------------------
// C[M,N] = A[M,K] @ B[K,N] (+bias). BM=128, BN=128, BK=16.
// 256 threads = 8 warps in 2(M) x 4(N); warp tile 64x32 via m16n8k8 tf32 mma.
// Each operand split hi/lo (round-to-nearest tf32); 3 mma terms per product:
//   a*b ~= a_lo*b_hi + a_hi*b_lo + a_hi*b_hi   (error ~2^-22, fp32-class)
// Requires K % 16 == 0, N % 128 == 0. M guarded.

__device__ __forceinline__ void cp_async16(void* smem_dst, const void* gmem_src) {
    uint32_t s = (uint32_t)__cvta_generic_to_shared(smem_dst);
    asm volatile("cp.async.cg.shared.global [%0], [%1], 16;\n" :: "r"(s), "l"(gmem_src));
}

__device__ __forceinline__ uint32_t f2tf32(float x) {
    uint32_t r;
    asm("cvt.rna.tf32.f32 %0, %1;\n" : "=r"(r) : "f"(x));
    return r;
}

__device__ __forceinline__ void split_tf32(float v, uint32_t& hi, uint32_t& lo) {
    hi = f2tf32(v);
    lo = f2tf32(v - __uint_as_float(hi));
}

__device__ __forceinline__ void mma_tf32_16x8x8(
    float& c0, float& c1, float& c2, float& c3,
    uint32_t a0, uint32_t a1, uint32_t a2, uint32_t a3,
    uint32_t b0, uint32_t b1)
{
    asm volatile(
        "mma.sync.aligned.m16n8k8.row.col.f32.tf32.tf32.f32 "
        "{%0,%1,%2,%3}, {%4,%5,%6,%7}, {%8,%9}, {%0,%1,%2,%3};\n"
        : "+f"(c0), "+f"(c1), "+f"(c2), "+f"(c3)
        : "r"(a0), "r"(a1), "r"(a2), "r"(a3), "r"(b0), "r"(b1));
}

#define AS_STRIDE 20   // 16 + 4 pad: conflict-free for A-frag pattern
#define BS_STRIDE 136  // 128 + 8 pad: conflict-free for B-frag pattern

__global__ __launch_bounds__(256) void gemm_tf32x3_kernel(
    const float* __restrict__ A, const float* __restrict__ B,
    float* __restrict__ C, int M, int N, int K, const float* __restrict__ bias)
{
    __shared__ float As[2][128][AS_STRIDE];
    __shared__ float Bs[2][16][BS_STRIDE];

    const int tid  = threadIdx.x;
    const int warp = tid >> 5;
    const int lane = tid & 31;
    const int g    = lane >> 2;   // group id 0..7
    const int t    = lane & 3;    // thread-in-group 0..3

    const int rowBase = blockIdx.y * 128;
    const int colBase = blockIdx.x * 128;
    const int mBase = (warp >> 2) * 64;   // warp M offset in tile
    const int nBase = (warp & 3) * 32;    // warp N offset in tile

    float acc[4][4][4];
    #pragma unroll
    for (int i = 0; i < 4; i++)
        #pragma unroll
        for (int j = 0; j < 4; j++)
            #pragma unroll
            for (int c = 0; c < 4; c++) acc[i][j][c] = 0.0f;

    const int nTiles = K >> 4;

    // A copy mapping: 512 float4 slots (128 rows x 4), 2 per thread
    const int am0 = (tid + 0)   >> 2, aq0 = (tid + 0)   & 3;
    const int am1 = (tid + 256) >> 2, aq1 = (tid + 256) & 3;
    // B copy mapping: 512 float4 slots (16 rows x 32), 2 per thread
    const int bk0 = (tid + 0)   >> 5, bq0 = (tid + 0)   & 31;
    const int bk1 = (tid + 256) >> 5, bq1 = (tid + 256) & 31;

    auto issue_tile = [&](int tIdx, int buf) {
        int k0 = tIdx << 4;
        int ga0 = rowBase + am0;
        int ga1 = rowBase + am1;
        if (ga0 < M) cp_async16(&As[buf][am0][aq0 * 4], A + (size_t)ga0 * K + k0 + aq0 * 4);
        if (ga1 < M) cp_async16(&As[buf][am1][aq1 * 4], A + (size_t)ga1 * K + k0 + aq1 * 4);
        cp_async16(&Bs[buf][bk0][bq0 * 4], B + (size_t)(k0 + bk0) * N + colBase + bq0 * 4);
        cp_async16(&Bs[buf][bk1][bq1 * 4], B + (size_t)(k0 + bk1) * N + colBase + bq1 * 4);
        asm volatile("cp.async.commit_group;\n");
    };

    issue_tile(0, 0);

    for (int tIdx = 0; tIdx < nTiles; tIdx++) {
        int buf = tIdx & 1;
        bool hasNext = (tIdx + 1) < nTiles;
        if (hasNext) issue_tile(tIdx + 1, buf ^ 1);
        if (hasNext) asm volatile("cp.async.wait_group 1;\n");
        else         asm volatile("cp.async.wait_group 0;\n");
        __syncthreads();

        #pragma unroll
        for (int ks = 0; ks < 16; ks += 8) {
            uint32_t ah[4][4], al[4][4];
            #pragma unroll
            for (int mi = 0; mi < 4; mi++) {
                int r = mBase + mi * 16 + g;
                split_tf32(As[buf][r    ][ks + t    ], ah[mi][0], al[mi][0]);
                split_tf32(As[buf][r + 8][ks + t    ], ah[mi][1], al[mi][1]);
                split_tf32(As[buf][r    ][ks + t + 4], ah[mi][2], al[mi][2]);
                split_tf32(As[buf][r + 8][ks + t + 4], ah[mi][3], al[mi][3]);
            }
            uint32_t bh[4][2], bl[4][2];
            #pragma unroll
            for (int ni = 0; ni < 4; ni++) {
                int c = nBase + ni * 8 + g;
                split_tf32(Bs[buf][ks + t    ][c], bh[ni][0], bl[ni][0]);
                split_tf32(Bs[buf][ks + t + 4][c], bh[ni][1], bl[ni][1]);
            }
            #pragma unroll
            for (int mi = 0; mi < 4; mi++)
                #pragma unroll
                for (int ni = 0; ni < 4; ni++) {
                    // small terms first, big term last
                    mma_tf32_16x8x8(acc[mi][ni][0], acc[mi][ni][1],
                                    acc[mi][ni][2], acc[mi][ni][3],
                                    al[mi][0], al[mi][1], al[mi][2], al[mi][3],
                                    bh[ni][0], bh[ni][1]);
                    mma_tf32_16x8x8(acc[mi][ni][0], acc[mi][ni][1],
                                    acc[mi][ni][2], acc[mi][ni][3],
                                    ah[mi][0], ah[mi][1], ah[mi][2], ah[mi][3],
                                    bl[ni][0], bl[ni][1]);
                    mma_tf32_16x8x8(acc[mi][ni][0], acc[mi][ni][1],
                                    acc[mi][ni][2], acc[mi][ni][3],
                                    ah[mi][0], ah[mi][1], ah[mi][2], ah[mi][3],
                                    bh[ni][0], bh[ni][1]);
                }
        }
        __syncthreads();
    }

    // epilogue
    #pragma unroll
    for (int mi = 0; mi < 4; mi++) {
        int r0 = rowBase + mBase + mi * 16 + g;
        int r1 = r0 + 8;
        #pragma unroll
        for (int ni = 0; ni < 4; ni++) {
            int c = colBase + nBase + ni * 8 + 2 * t;
            float b0 = 0.f, b1 = 0.f;
            if (bias) { b0 = bias[c]; b1 = bias[c + 1]; }
            if (r0 < M) {
                float2 v = make_float2(acc[mi][ni][0] + b0, acc[mi][ni][1] + b1);
                *(float2*)(C + (size_t)r0 * N + c) = v;
            }
            if (r1 < M) {
                float2 v = make_float2(acc[mi][ni][2] + b0, acc[mi][ni][3] + b1);
                *(float2*)(C + (size_t)r1 * N + c) = v;
            }
        }
    }
}

// ---------------- aggregation: warp per node --------------------------------
// layer 1: h1 = relu( mean_j t[j,0:128] + b_l1 + t[i,128:256] )
__global__ __launch_bounds__(256) void agg1_kernel(const float* __restrict__ b_l1) {
    int node = (blockIdx.x * blockDim.x + threadIdx.x) >> 5;
    int lane = threadIdx.x & 31;
    if (node >= N_NODES) return;
    int s = g_off[node], e = g_off[node + 1];
    float4 a0 = make_float4(0.f, 0.f, 0.f, 0.f);
    float4 a1 = make_float4(0.f, 0.f, 0.f, 0.f);
    int i = s;
    for (; i + 3 < e; i += 4) {
        int s0 = g_csr[i], s1 = g_csr[i + 1], s2 = g_csr[i + 2], s3 = g_csr[i + 3];
        float4 v0 = *(const float4*)(g_t + (size_t)s0 * 256 + lane * 4);
        float4 v1 = *(const float4*)(g_t + (size_t)s1 * 256 + lane * 4);
        float4 v2 = *(const float4*)(g_t + (size_t)s2 * 256 + lane * 4);
        float4 v3 = *(const float4*)(g_t + (size_t)s3 * 256 + lane * 4);
        a0.x += v0.x + v1.x; a0.y += v0.y + v1.y; a0.z += v0.z + v1.z; a0.w += v0.w + v1.w;
        a1.x += v2.x + v3.x; a1.y += v2.y + v3.y; a1.z += v2.z + v3.z; a1.w += v2.w + v3.w;
    }
    for (; i < e; i++) {
        int s0 = g_csr[i];
        float4 v0 = *(const float4*)(g_t + (size_t)s0 * 256 + lane * 4);
        a0.x += v0.x; a0.y += v0.y; a0.z += v0.z; a0.w += v0.w;
    }
    float inv = 1.0f / fmaxf((float)(e - s), 1.0f);
    float4 r  = *(const float4*)(g_t + (size_t)node * 256 + 128 + lane * 4);
    float4 bb = *(const float4*)(b_l1 + lane * 4);
    float4 o;
    o.x = fmaxf((a0.x + a1.x) * inv + bb.x + r.x, 0.f);
    o.y = fmaxf((a0.y + a1.y) * inv + bb.y + r.y, 0.f);
    o.z = fmaxf((a0.z + a1.z) * inv + bb.z + r.z, 0.f);
    o.w = fmaxf((a0.w + a1.w) * inv + bb.w + r.w, 0.f);
    *(float4*)(g_h1 + (size_t)node * HID + lane * 4) = o;
}

// layer 2 aggregation: g_t[i] = [ mean_j h1[j] | h1[i] ]
__global__ __launch_bounds__(256) void agg2_kernel() {
    int node = (blockIdx.x * blockDim.x + threadIdx.x) >> 5;
    int lane = threadIdx.x & 31;
    if (node >= N_NODES) return;
    int s = g_off[node], e = g_off[node + 1];
    float4 a0 = make_float4(0.f, 0.f, 0.f, 0.f);
    float4 a1 = make_float4(0.f, 0.f, 0.f, 0.f);
    int i = s;
    for (; i + 3 < e; i += 4) {
        int s0 = g_csr[i], s1 = g_csr[i + 1], s2 = g_csr[i + 2], s3 = g_csr[i + 3];
        float4 v0 = *(const float4*)(g_h1 + (size_t)s0 * HID + lane * 4);
        float4 v1 = *(const float4*)(g_h1 + (size_t)s1 * HID + lane * 4);
        float4 v2 = *(const float4*)(g_h1 + (size_t)s2 * HID + lane * 4);
        float4 v3 = *(const float4*)(g_h1 + (size_t)s3 * HID + lane * 4);
        a0.x += v0.x + v1.x; a0.y += v0.y + v1.y; a0.z += v0.z + v1.z; a0.w += v0.w + v1.w;
        a1.x += v2.x + v3.x; a1.y += v2.y + v3.y; a1.z += v2.z + v3.z; a1.w += v2.w + v3.w;
    }
    for (; i < e; i++) {
        int s0 = g_csr[i];
        float4 v0 = *(const float4*)(g_h1 + (size_t)s0 * HID + lane * 4);
        a0.x += v0.x; a0.y += v0.y; a0.z += v0.z; a0.w += v0.w;
    }
    float inv = 1.0f / fmaxf((float)(e - s), 1.0f);
    float4 o;
    o.x = (a0.x + a1.x) * inv;
    o.y = (a0.y + a1.y) * inv;
    o.z = (a0.z + a1.z) * inv;
    o.w = (a0.w + a1.w) * inv;
    *(float4*)(g_t + (size_t)node * 256 + lane * 4) = o;
    float4 own = *(const float4*)(g_h1 + (size_t)node * HID + lane * 4);
    *(float4*)(g_t + (size_t)node * 256 + 128 + lane * 4) = own;
}

// ---------------- decoder factorization ------------------------------------
// s_a[i] = h2[i] . W_lin[0:128], s_b[i] = h2[i] . W_lin[128:256]
__global__ __launch_bounds__(256) void sab_kernel(const float* __restrict__ W_lin) {
    int node = (blockIdx.x * blockDim.x + threadIdx.x) >> 5;
    int lane = threadIdx.x & 31;
    if (node >= N_NODES) return;
    float4 h  = *(const float4*)(g_h2 + (size_t)node * HID + lane * 4);
    float4 wa = *(const float4*)(W_lin + lane * 4);
    float4 wb = *(const float4*)(W_lin + 128 + lane * 4);
    float da = h.x * wa.x + h.y * wa.y + h.z * wa.z + h.w * wa.w;
    float db = h.x * wb.x + h.y * wb.y + h.z * wb.z + h.w * wb.w;
    #pragma unroll
    for (int off = 16; off > 0; off >>= 1) {
        da += __shfl_xor_sync(0xffffffff, da, off);
        db += __shfl_xor_sync(0xffffffff, db, off);
    }
    if (lane == 0) {
        g_sa[node] = da;
        g_sb[node] = db;
    }
}

__global__ void score_kernel(const int* __restrict__ pos, const int* __restrict__ neg,
                             const float* __restrict__ b_lin, float* __restrict__ out)
{
    int idx = blockIdx.x * blockDim.x + threadIdx.x;
    if (idx >= 1000000) return;
    float b = b_lin[0];
    if (idx < 500000) {
        int s = pos[idx];
        int d = pos[500000 + idx];
        out[idx] = g_sa[s] + g_sb[d] + b;
    } else {
        int e = idx - 500000;
        int s = neg[e];
        int d = neg[500000 + e];
        out[idx] = g_sa[s] + g_sb[d] + b;
    }
}

// ---------------- launch ----------------------------------------------------
extern "C" void kernel_launch(void* const* d_in, const int* in_sizes, int n_in,
                              void* d_out, int out_size)
{
    const float* x     = (const float*)d_in[0];
    const int*   ei    = (const int*)  d_in[1];
    const int*   pos   = (const int*)  d_in[2];
    const int*   neg   = (const int*)  d_in[3];
    const float* W_l1  = (const float*)d_in[4];
    const float* b_l1  = (const float*)d_in[5];
    const float* W_r1  = (const float*)d_in[6];
    const float* W_l2  = (const float*)d_in[7];
    const float* b_l2  = (const float*)d_in[8];
    const float* W_r2  = (const float*)d_in[9];
    const float* W_lin = (const float*)d_in[10];
    const float* b_lin = (const float*)d_in[11];
    float*       out   = (float*)d_out;

    const int* e_src = ei;
    const int* e_dst = ei + N_EDGES;

    void *p_t, *p_h2, *p_W1, *p_W2;
    cudaGetSymbolAddress(&p_t,  g_t);
    cudaGetSymbolAddress(&p_h2, g_h2);
    cudaGetSymbolAddress(&p_W1, g_W1);
    cudaGetSymbolAddress(&p_W2, g_W2);

    // CSR build
    zero_cnt_kernel<<<(N_NODES + 255) / 256, 256>>>();
    hist_kernel<<<(N_EDGES + 255) / 256, 256>>>(e_dst);
    scan_kernel<<<1, 1024>>>();
    scatter_kernel<<<(N_EDGES + 255) / 256, 256>>>(e_src, e_dst);

    // pack weight blocks
    pack_w1_kernel<<<(IN_DIM * 256 + 255) / 256, 256>>>(W_l1, W_r1);
    pack_w2_kernel<<<(256 * HID + 255) / 256, 256>>>(W_l2, W_r2);

    // layer 1: t = x @ [W_l1 | W_r1]   (100000 x 384) @ (384 x 256)
    {
        dim3 grid(256 / 128, (N_NODES + 127) / 128);
        gemm_tf32x3_kernel<<<grid, 256>>>(x, (const float*)p_W1, (float*)p_t,
                                          N_NODES, 256, IN_DIM, nullptr);
    }
    // h1 = relu(mean-aggregate + b + root)
    agg1_kernel<<<(N_NODES * 32 + 255) / 256, 256>>>(b_l1);

    // layer 2: build [agg2 | h1], then h2 = that @ [W_l2 ; W_r2] + b_l2
    agg2_kernel<<<(N_NODES * 32 + 255) / 256, 256>>>();
    {
        dim3 grid(HID / 128, (N_NODES + 127) / 128);
        gemm_tf32x3_kernel<<<grid, 256>>>((const float*)p_t, (const float*)p_W2, (float*)p_h2,
                                          N_NODES, HID, 256, b_l2);
    }

    // decoder
    sab_kernel<<<(N_NODES * 32 + 255) / 256, 256>>>(W_lin);
    score_kernel<<<(1000000 + 255) / 256, 256>>>(pos, neg, b_lin, out);
}

// round 7
// speedup vs baseline: 1.4865x; 1.2610x over previous
#include <cuda_runtime.h>
#include <cstdint>

#define N_NODES 100000
#define N_EDGES 3200000
#define IN_DIM  384
#define HID     128
#define NB_SCAN ((N_NODES + 255) / 256)   // 391 scan blocks

// ---------------- scratch (device globals; no allocation allowed) ----------
__device__ int   g_cnt[N_NODES];
__device__ int   g_off[N_NODES + 1];
__device__ int   g_cur[N_NODES];
__device__ int   g_csr[N_EDGES];
__device__ int   g_bsum[512];
__device__ int   g_boff[512];
__device__ float g_t  [(size_t)N_NODES * 256];  // layer1 pre-transform [xWl1|xWr1]; reused as [agg2|h1]
__device__ float g_h1 [(size_t)N_NODES * HID];
__device__ float g_h2 [(size_t)N_NODES * HID];
__device__ float g_sa [N_NODES];
__device__ float g_sb [N_NODES];
__device__ float g_W1 [IN_DIM * 256];           // [W_l1 | W_r1]  (384 x 256)
__device__ float g_W2 [256 * HID];              // [W_l2 ; W_r2]  (256 x 128)

// ---------------- small utility kernels ------------------------------------
__global__ void zero_cnt_kernel() {
    int i = blockIdx.x * blockDim.x + threadIdx.x;
    if (i < N_NODES) g_cnt[i] = 0;
}

__global__ void pack_w1_kernel(const float* __restrict__ Wl, const float* __restrict__ Wr) {
    int idx = blockIdx.x * blockDim.x + threadIdx.x;
    if (idx >= IN_DIM * 256) return;
    int k = idx >> 8;
    int j = idx & 255;
    g_W1[idx] = (j < HID) ? Wl[k * HID + j] : Wr[k * HID + (j - HID)];
}

__global__ void pack_w2_kernel(const float* __restrict__ Wl, const float* __restrict__ Wr) {
    int idx = blockIdx.x * blockDim.x + threadIdx.x;
    if (idx >= 256 * HID) return;
    int k = idx >> 7;
    int j = idx & 127;
    g_W2[idx] = (k < HID) ? Wl[k * HID + j] : Wr[(k - HID) * HID + j];
}

__global__ void hist_kernel(const int* __restrict__ dst) {
    int e = blockIdx.x * blockDim.x + threadIdx.x;
    if (e < N_EDGES) atomicAdd(&g_cnt[dst[e]], 1);
}

// ---------------- 3-kernel decoupled exclusive scan -------------------------
// 1) per-block (256 elems) local exclusive scan + block sums
__global__ __launch_bounds__(256) void scan_local_kernel() {
    __shared__ int sw[8];
    int b = blockIdx.x, t = threadIdx.x;
    int idx = b * 256 + t;
    int v = (idx < N_NODES) ? g_cnt[idx] : 0;
    int lane = t & 31, wid = t >> 5;
    int x = v;
    #pragma unroll
    for (int o = 1; o < 32; o <<= 1) {
        int n = __shfl_up_sync(0xffffffff, x, o);
        if (lane >= o) x += n;
    }
    if (lane == 31) sw[wid] = x;
    __syncthreads();
    if (wid == 0) {
        int s = (lane < 8) ? sw[lane] : 0;
        #pragma unroll
        for (int o = 1; o < 8; o <<= 1) {
            int n = __shfl_up_sync(0xffffffff, s, o);
            if (lane >= o) s += n;
        }
        if (lane < 8) sw[lane] = s;
    }
    __syncthreads();
    int warpoff = (wid > 0) ? sw[wid - 1] : 0;
    int incl = warpoff + x;
    if (idx < N_NODES) g_off[idx] = incl - v;   // block-local exclusive
    if (t == 255) g_bsum[b] = incl;             // block total
}

// 2) scan of the block sums (one block, 512 threads, NB_SCAN <= 512)
__global__ __launch_bounds__(512) void scan_bsum_kernel() {
    __shared__ int sw[16];
    int t = threadIdx.x;
    int v = (t < NB_SCAN) ? g_bsum[t] : 0;
    int lane = t & 31, wid = t >> 5;
    int x = v;
    #pragma unroll
    for (int o = 1; o < 32; o <<= 1) {
        int n = __shfl_up_sync(0xffffffff, x, o);
        if (lane >= o) x += n;
    }
    if (lane == 31) sw[wid] = x;
    __syncthreads();
    if (wid == 0) {
        int s = (lane < 16) ? sw[lane] : 0;
        #pragma unroll
        for (int o = 1; o < 16; o <<= 1) {
            int n = __shfl_up_sync(0xffffffff, s, o);
            if (lane >= o) s += n;
        }
        if (lane < 16) sw[lane] = s;
    }
    __syncthreads();
    int warpoff = (wid > 0) ? sw[wid - 1] : 0;
    int incl = warpoff + x;
    if (t < NB_SCAN) g_boff[t] = incl - v;
    if (t == 511) g_off[N_NODES] = incl;        // grand total (v=0 beyond NB_SCAN)
}

// 3) add block offsets; init cursor
__global__ __launch_bounds__(256) void scan_add_kernel() {
    int idx = blockIdx.x * 256 + threadIdx.x;
    if (idx >= N_NODES) return;
    int o = g_off[idx] + g_boff[blockIdx.x];
    g_off[idx] = o;
    g_cur[idx] = o;
}

__global__ void scatter_kernel(const int* __restrict__ src, const int* __restrict__ dst) {
    int e = blockIdx.x * blockDim.x + threadIdx.x;
    if (e >= N_EDGES) return;
    int p = atomicAdd(&g_cur[dst[e]], 1);
    g_csr[p] = src[e];
}

// ---------------- TF32 tensor-core GEMM ------------------------------------
// C[M,N] = A[M,K] @ B[K,N] (+bias). BM=128, BN=128, BK=16.
// 256 threads = 8 warps in 2(M) x 4(N); warp tile 64x32 via m16n8k8 tf32 mma.
// TERMS==3: Markidis hi/lo split, fp32-class accuracy (3 mma per product).
// TERMS==1: single rna-tf32 mma (~2^-12 unbiased per-element error).
// Requires K % 16 == 0, N % 128 == 0. M guarded.

__device__ __forceinline__ void cp_async16(void* smem_dst, const void* gmem_src) {
    uint32_t s = (uint32_t)__cvta_generic_to_shared(smem_dst);
    asm volatile("cp.async.cg.shared.global [%0], [%1], 16;\n" :: "r"(s), "l"(gmem_src));
}

__device__ __forceinline__ uint32_t f2tf32(float x) {
    uint32_t r;
    asm("cvt.rna.tf32.f32 %0, %1;\n" : "=r"(r) : "f"(x));
    return r;
}

__device__ __forceinline__ void split_tf32(float v, uint32_t& hi, uint32_t& lo) {
    hi = f2tf32(v);
    lo = f2tf32(v - __uint_as_float(hi));
}

__device__ __forceinline__ void mma_tf32_16x8x8(
    float& c0, float& c1, float& c2, float& c3,
    uint32_t a0, uint32_t a1, uint32_t a2, uint32_t a3,
    uint32_t b0, uint32_t b1)
{
    asm volatile(
        "mma.sync.aligned.m16n8k8.row.col.f32.tf32.tf32.f32 "
        "{%0,%1,%2,%3}, {%4,%5,%6,%7}, {%8,%9}, {%0,%1,%2,%3};\n"
        : "+f"(c0), "+f"(c1), "+f"(c2), "+f"(c3)
        : "r"(a0), "r"(a1), "r"(a2), "r"(a3), "r"(b0), "r"(b1));
}

#define AS_STRIDE 20   // 16 + 4 pad: conflict-free for A-frag pattern
#define BS_STRIDE 136  // 128 + 8 pad: conflict-free for B-frag pattern

template<int TERMS>
__global__ __launch_bounds__(256) void gemm_tf32_kernel(
    const float* __restrict__ A, const float* __restrict__ B,
    float* __restrict__ C, int M, int N, int K, const float* __restrict__ bias)
{
    __shared__ float As[2][128][AS_STRIDE];
    __shared__ float Bs[2][16][BS_STRIDE];

    const int tid  = threadIdx.x;
    const int warp = tid >> 5;
    const int lane = tid & 31;
    const int g    = lane >> 2;
    const int t    = lane & 3;

    const int rowBase = blockIdx.y * 128;
    const int colBase = blockIdx.x * 128;
    const int mBase = (warp >> 2) * 64;
    const int nBase = (warp & 3) * 32;

    float acc[4][4][4];
    #pragma unroll
    for (int i = 0; i < 4; i++)
        #pragma unroll
        for (int j = 0; j < 4; j++)
            #pragma unroll
            for (int c = 0; c < 4; c++) acc[i][j][c] = 0.0f;

    const int nTiles = K >> 4;

    const int am0 = (tid + 0)   >> 2, aq0 = (tid + 0)   & 3;
    const int am1 = (tid + 256) >> 2, aq1 = (tid + 256) & 3;
    const int bk0 = (tid + 0)   >> 5, bq0 = (tid + 0)   & 31;
    const int bk1 = (tid + 256) >> 5, bq1 = (tid + 256) & 31;

    auto issue_tile = [&](int tIdx, int buf) {
        int k0 = tIdx << 4;
        int ga0 = rowBase + am0;
        int ga1 = rowBase + am1;
        if (ga0 < M) cp_async16(&As[buf][am0][aq0 * 4], A + (size_t)ga0 * K + k0 + aq0 * 4);
        if (ga1 < M) cp_async16(&As[buf][am1][aq1 * 4], A + (size_t)ga1 * K + k0 + aq1 * 4);
        cp_async16(&Bs[buf][bk0][bq0 * 4], B + (size_t)(k0 + bk0) * N + colBase + bq0 * 4);
        cp_async16(&Bs[buf][bk1][bq1 * 4], B + (size_t)(k0 + bk1) * N + colBase + bq1 * 4);
        asm volatile("cp.async.commit_group;\n");
    };

    issue_tile(0, 0);

    for (int tIdx = 0; tIdx < nTiles; tIdx++) {
        int buf = tIdx & 1;
        bool hasNext = (tIdx + 1) < nTiles;
        if (hasNext) issue_tile(tIdx + 1, buf ^ 1);
        if (hasNext) asm volatile("cp.async.wait_group 1;\n");
        else         asm volatile("cp.async.wait_group 0;\n");
        __syncthreads();

        #pragma unroll
        for (int ks = 0; ks < 16; ks += 8) {
            uint32_t ah[4][4], al[4][4];
            #pragma unroll
            for (int mi = 0; mi < 4; mi++) {
                int r = mBase + mi * 16 + g;
                if (TERMS == 3) {
                    split_tf32(As[buf][r    ][ks + t    ], ah[mi][0], al[mi][0]);
                    split_tf32(As[buf][r + 8][ks + t    ], ah[mi][1], al[mi][1]);
                    split_tf32(As[buf][r    ][ks + t + 4], ah[mi][2], al[mi][2]);
                    split_tf32(As[buf][r + 8][ks + t + 4], ah[mi][3], al[mi][3]);
                } else {
                    ah[mi][0] = f2tf32(As[buf][r    ][ks + t    ]);
                    ah[mi][1] = f2tf32(As[buf][r + 8][ks + t    ]);
                    ah[mi][2] = f2tf32(As[buf][r    ][ks + t + 4]);
                    ah[mi][3] = f2tf32(As[buf][r + 8][ks + t + 4]);
                }
            }
            uint32_t bh[4][2], bl[4][2];
            #pragma unroll
            for (int ni = 0; ni < 4; ni++) {
                int c = nBase + ni * 8 + g;
                if (TERMS == 3) {
                    split_tf32(Bs[buf][ks + t    ][c], bh[ni][0], bl[ni][0]);
                    split_tf32(Bs[buf][ks + t + 4][c], bh[ni][1], bl[ni][1]);
                } else {
                    bh[ni][0] = f2tf32(Bs[buf][ks + t    ][c]);
                    bh[ni][1] = f2tf32(Bs[buf][ks + t + 4][c]);
                }
            }
            #pragma unroll
            for (int mi = 0; mi < 4; mi++)
                #pragma unroll
                for (int ni = 0; ni < 4; ni++) {
                    if (TERMS == 3) {
                        mma_tf32_16x8x8(acc[mi][ni][0], acc[mi][ni][1],
                                        acc[mi][ni][2], acc[mi][ni][3],
                                        al[mi][0], al[mi][1], al[mi][2], al[mi][3],
                                        bh[ni][0], bh[ni][1]);
                        mma_tf32_16x8x8(acc[mi][ni][0], acc[mi][ni][1],
                                        acc[mi][ni][2], acc[mi][ni][3],
                                        ah[mi][0], ah[mi][1], ah[mi][2], ah[mi][3],
                                        bl[ni][0], bl[ni][1]);
                    }
                    mma_tf32_16x8x8(acc[mi][ni][0], acc[mi][ni][1],
                                    acc[mi][ni][2], acc[mi][ni][3],
                                    ah[mi][0], ah[mi][1], ah[mi][2], ah[mi][3],
                                    bh[ni][0], bh[ni][1]);
                }
        }
        __syncthreads();
    }

    #pragma unroll
    for (int mi = 0; mi < 4; mi++) {
        int r0 = rowBase + mBase + mi * 16 + g;
        int r1 = r0 + 8;
        #pragma unroll
        for (int ni = 0; ni < 4; ni++) {
            int c = colBase + nBase + ni * 8 + 2 * t;
            float b0 = 0.f, b1 = 0.f;
            if (bias) { b0 = bias[c]; b1 = bias[c + 1]; }
            if (r0 < M) {
                float2 v = make_float2(acc[mi][ni][0] + b0, acc[mi][ni][1] + b1);
                *(float2*)(C + (size_t)r0 * N + c) = v;
            }
            if (r1 < M) {
                float2 v = make_float2(acc[mi][ni][2] + b0, acc[mi][ni][3] + b1);
                *(float2*)(C + (size_t)r1 * N + c) = v;
            }
        }
    }
}

// ---------------- aggregation: warp per node, 8-deep MLP --------------------
// layer 1: h1 = relu( mean_j t[j,0:128] + b_l1 + t[i,128:256] )
__global__ __launch_bounds__(256) void agg1_kernel(const float* __restrict__ b_l1) {
    int node = (blockIdx.x * blockDim.x + threadIdx.x) >> 5;
    int lane = threadIdx.x & 31;
    if (node >= N_NODES) return;
    int s = g_off[node], e = g_off[node + 1];
    float4 a0 = make_float4(0.f, 0.f, 0.f, 0.f);
    float4 a1 = make_float4(0.f, 0.f, 0.f, 0.f);
    int i = s;
    for (; i + 7 < e; i += 8) {
        int sj[8];
        #pragma unroll
        for (int u = 0; u < 8; u++) sj[u] = g_csr[i + u];
        float4 v[8];
        #pragma unroll
        for (int u = 0; u < 8; u++)
            v[u] = *(const float4*)(g_t + (size_t)sj[u] * 256 + lane * 4);
        #pragma unroll
        for (int u = 0; u < 4; u++) {
            a0.x += v[u].x; a0.y += v[u].y; a0.z += v[u].z; a0.w += v[u].w;
        }
        #pragma unroll
        for (int u = 4; u < 8; u++) {
            a1.x += v[u].x; a1.y += v[u].y; a1.z += v[u].z; a1.w += v[u].w;
        }
    }
    for (; i < e; i++) {
        int s0 = g_csr[i];
        float4 v0 = *(const float4*)(g_t + (size_t)s0 * 256 + lane * 4);
        a0.x += v0.x; a0.y += v0.y; a0.z += v0.z; a0.w += v0.w;
    }
    float inv = 1.0f / fmaxf((float)(e - s), 1.0f);
    float4 r  = *(const float4*)(g_t + (size_t)node * 256 + 128 + lane * 4);
    float4 bb = *(const float4*)(b_l1 + lane * 4);
    float4 o;
    o.x = fmaxf((a0.x + a1.x) * inv + bb.x + r.x, 0.f);
    o.y = fmaxf((a0.y + a1.y) * inv + bb.y + r.y, 0.f);
    o.z = fmaxf((a0.z + a1.z) * inv + bb.z + r.z, 0.f);
    o.w = fmaxf((a0.w + a1.w) * inv + bb.w + r.w, 0.f);
    *(float4*)(g_h1 + (size_t)node * HID + lane * 4) = o;
}

// layer 2 aggregation: g_t[i] = [ mean_j h1[j] | h1[i] ]
__global__ __launch_bounds__(256) void agg2_kernel() {
    int node = (blockIdx.x * blockDim.x + threadIdx.x) >> 5;
    int lane = threadIdx.x & 31;
    if (node >= N_NODES) return;
    int s = g_off[node], e = g_off[node + 1];
    float4 a0 = make_float4(0.f, 0.f, 0.f, 0.f);
    float4 a1 = make_float4(0.f, 0.f, 0.f, 0.f);
    int i = s;
    for (; i + 7 < e; i += 8) {
        int sj[8];
        #pragma unroll
        for (int u = 0; u < 8; u++) sj[u] = g_csr[i + u];
        float4 v[8];
        #pragma unroll
        for (int u = 0; u < 8; u++)
            v[u] = *(const float4*)(g_h1 + (size_t)sj[u] * HID + lane * 4);
        #pragma unroll
        for (int u = 0; u < 4; u++) {
            a0.x += v[u].x; a0.y += v[u].y; a0.z += v[u].z; a0.w += v[u].w;
        }
        #pragma unroll
        for (int u = 4; u < 8; u++) {
            a1.x += v[u].x; a1.y += v[u].y; a1.z += v[u].z; a1.w += v[u].w;
        }
    }
    for (; i < e; i++) {
        int s0 = g_csr[i];
        float4 v0 = *(const float4*)(g_h1 + (size_t)s0 * HID + lane * 4);
        a0.x += v0.x; a0.y += v0.y; a0.z += v0.z; a0.w += v0.w;
    }
    float inv = 1.0f / fmaxf((float)(e - s), 1.0f);
    float4 o;
    o.x = (a0.x + a1.x) * inv;
    o.y = (a0.y + a1.y) * inv;
    o.z = (a0.z + a1.z) * inv;
    o.w = (a0.w + a1.w) * inv;
    *(float4*)(g_t + (size_t)node * 256 + lane * 4) = o;
    float4 own = *(const float4*)(g_h1 + (size_t)node * HID + lane * 4);
    *(float4*)(g_t + (size_t)node * 256 + 128 + lane * 4) = own;
}

// ---------------- decoder factorization ------------------------------------
__global__ __launch_bounds__(256) void sab_kernel(const float* __restrict__ W_lin) {
    int node = (blockIdx.x * blockDim.x + threadIdx.x) >> 5;
    int lane = threadIdx.x & 31;
    if (node >= N_NODES) return;
    float4 h  = *(const float4*)(g_h2 + (size_t)node * HID + lane * 4);
    float4 wa = *(const float4*)(W_lin + lane * 4);
    float4 wb = *(const float4*)(W_lin + 128 + lane * 4);
    float da = h.x * wa.x + h.y * wa.y + h.z * wa.z + h.w * wa.w;
    float db = h.x * wb.x + h.y * wb.y + h.z * wb.z + h.w * wb.w;
    #pragma unroll
    for (int off = 16; off > 0; off >>= 1) {
        da += __shfl_xor_sync(0xffffffff, da, off);
        db += __shfl_xor_sync(0xffffffff, db, off);
    }
    if (lane == 0) {
        g_sa[node] = da;
        g_sb[node] = db;
    }
}

__global__ void score_kernel(const int* __restrict__ pos, const int* __restrict__ neg,
                             const float* __restrict__ b_lin, float* __restrict__ out)
{
    int idx = blockIdx.x * blockDim.x + threadIdx.x;
    if (idx >= 1000000) return;
    float b = b_lin[0];
    if (idx < 500000) {
        int s = pos[idx];
        int d = pos[500000 + idx];
        out[idx] = g_sa[s] + g_sb[d] + b;
    } else {
        int e = idx - 500000;
        int s = neg[e];
        int d = neg[500000 + e];
        out[idx] = g_sa[s] + g_sb[d] + b;
    }
}

// ---------------- launch ----------------------------------------------------
extern "C" void kernel_launch(void* const* d_in, const int* in_sizes, int n_in,
                              void* d_out, int out_size)
{
    const float* x     = (const float*)d_in[0];
    const int*   ei    = (const int*)  d_in[1];
    const int*   pos   = (const int*)  d_in[2];
    const int*   neg   = (const int*)  d_in[3];
    const float* W_l1  = (const float*)d_in[4];
    const float* b_l1  = (const float*)d_in[5];
    const float* W_r1  = (const float*)d_in[6];
    const float* W_l2  = (const float*)d_in[7];
    const float* b_l2  = (const float*)d_in[8];
    const float* W_r2  = (const float*)d_in[9];
    const float* W_lin = (const float*)d_in[10];
    const float* b_lin = (const float*)d_in[11];
    float*       out   = (float*)d_out;

    const int* e_src = ei;
    const int* e_dst = ei + N_EDGES;

    void *p_t, *p_h2, *p_W1, *p_W2;
    cudaGetSymbolAddress(&p_t,  g_t);
    cudaGetSymbolAddress(&p_h2, g_h2);
    cudaGetSymbolAddress(&p_W1, g_W1);
    cudaGetSymbolAddress(&p_W2, g_W2);

    // CSR build
    zero_cnt_kernel<<<(N_NODES + 255) / 256, 256>>>();
    hist_kernel<<<(N_EDGES + 255) / 256, 256>>>(e_dst);
    scan_local_kernel<<<NB_SCAN, 256>>>();
    scan_bsum_kernel<<<1, 512>>>();
    scan_add_kernel<<<NB_SCAN, 256>>>();
    scatter_kernel<<<(N_EDGES + 255) / 256, 256>>>(e_src, e_dst);

    // pack weight blocks
    pack_w1_kernel<<<(IN_DIM * 256 + 255) / 256, 256>>>(W_l1, W_r1);
    pack_w2_kernel<<<(256 * HID + 255) / 256, 256>>>(W_l2, W_r2);

    // layer 1: t = x @ [W_l1 | W_r1]   (100000 x 384) @ (384 x 256), fp32-class
    {
        dim3 grid(256 / 128, (N_NODES + 127) / 128);
        gemm_tf32_kernel<3><<<grid, 256>>>(x, (const float*)p_W1, (float*)p_t,
                                           N_NODES, 256, IN_DIM, nullptr);
    }
    // h1 = relu(mean-aggregate + b + root)
    agg1_kernel<<<(N_NODES * 32 + 255) / 256, 256>>>(b_l1);

    // layer 2: build [agg2 | h1], then h2 = that @ [W_l2 ; W_r2] + b_l2 (1-term rna tf32)
    agg2_kernel<<<(N_NODES * 32 + 255) / 256, 256>>>();
    {
        dim3 grid(HID / 128, (N_NODES + 127) / 128);
        gemm_tf32_kernel<1><<<grid, 256>>>((const float*)p_t, (const float*)p_W2, (float*)p_h2,
                                           N_NODES, HID, 256, b_l2);
    }

    // decoder
    sab_kernel<<<(N_NODES * 32 + 255) / 256, 256>>>(W_lin);
    score_kernel<<<(1000000 + 255) / 256, 256>>>(pos, neg, b_lin, out);
}

// round 10
// speedup vs baseline: 1.8182x; 1.2231x over previous
#include <cuda_runtime.h>
#include <cstdint>

#define N_NODES 100000
#define N_EDGES 3200000
#define IN_DIM  384
#define HID     128
#define NB_SCAN ((N_NODES + 255) / 256)   // 391 scan blocks

// ---------------- scratch (device globals; no allocation allowed) ----------
__device__ int   g_cnt[N_NODES];
__device__ int   g_off[N_NODES + 1];
__device__ int   g_cur[N_NODES];
__device__ int   g_csr[N_EDGES];
__device__ int   g_bsum[512];
__device__ int   g_boff[512];
__device__ float g_t  [(size_t)N_NODES * 256];  // layer1 pre-transform [xWl1|xWr1]
__device__ float g_h1 [(size_t)N_NODES * HID];
__device__ float g_sa [N_NODES];
__device__ float g_sb [N_NODES];
__device__ float g_W1 [IN_DIM * 256];           // [W_l1 | W_r1]  (384 x 256)
__device__ float g_w2a[256];                    // W2 @ wa (decoder-folded layer-2 weights)
__device__ float g_w2b[256];                    // W2 @ wb
__device__ float g_c  [2];                      // b_l2 . wa, b_l2 . wb

// ---------------- small utility kernels ------------------------------------
__global__ void zero_cnt_kernel() {
    int i = blockIdx.x * blockDim.x + threadIdx.x;
    if (i < N_NODES) g_cnt[i] = 0;
}

__global__ void pack_w1_kernel(const float* __restrict__ Wl, const float* __restrict__ Wr) {
    int idx = blockIdx.x * blockDim.x + threadIdx.x;
    if (idx >= IN_DIM * 256) return;
    int k = idx >> 8;
    int j = idx & 255;
    g_W1[idx] = (j < HID) ? Wl[k * HID + j] : Wr[k * HID + (j - HID)];
}

// decoder fold: w2a[k] = sum_j W2[k][j]*W_lin[j],  w2b[k] = sum_j W2[k][j]*W_lin[128+j]
// W2 = [W_l2 ; W_r2] stacked (256 x 128). Also the bias scalars.
__global__ void decoder_pre_kernel(const float* __restrict__ Wl2, const float* __restrict__ Wr2,
                                   const float* __restrict__ b_l2, const float* __restrict__ W_lin)
{
    int k = blockIdx.x * blockDim.x + threadIdx.x;
    if (k >= 256) return;
    const float* row = (k < HID) ? (Wl2 + (size_t)k * HID) : (Wr2 + (size_t)(k - HID) * HID);
    float sa = 0.f, sb = 0.f;
    for (int j = 0; j < HID; j++) {
        float w = row[j];
        sa += w * W_lin[j];
        sb += w * W_lin[HID + j];
    }
    g_w2a[k] = sa;
    g_w2b[k] = sb;
    if (k == 0) {
        float ca = 0.f, cb = 0.f;
        for (int j = 0; j < HID; j++) {
            ca += b_l2[j] * W_lin[j];
            cb += b_l2[j] * W_lin[HID + j];
        }
        g_c[0] = ca;
        g_c[1] = cb;
    }
}

__global__ void hist_kernel(const int* __restrict__ dst) {
    int e = blockIdx.x * blockDim.x + threadIdx.x;
    if (e < N_EDGES) atomicAdd(&g_cnt[dst[e]], 1);
}

// ---------------- 3-kernel decoupled exclusive scan -------------------------
__global__ __launch_bounds__(256) void scan_local_kernel() {
    __shared__ int sw[8];
    int b = blockIdx.x, t = threadIdx.x;
    int idx = b * 256 + t;
    int v = (idx < N_NODES) ? g_cnt[idx] : 0;
    int lane = t & 31, wid = t >> 5;
    int x = v;
    #pragma unroll
    for (int o = 1; o < 32; o <<= 1) {
        int n = __shfl_up_sync(0xffffffff, x, o);
        if (lane >= o) x += n;
    }
    if (lane == 31) sw[wid] = x;
    __syncthreads();
    if (wid == 0) {
        int s = (lane < 8) ? sw[lane] : 0;
        #pragma unroll
        for (int o = 1; o < 8; o <<= 1) {
            int n = __shfl_up_sync(0xffffffff, s, o);
            if (lane >= o) s += n;
        }
        if (lane < 8) sw[lane] = s;
    }
    __syncthreads();
    int warpoff = (wid > 0) ? sw[wid - 1] : 0;
    int incl = warpoff + x;
    if (idx < N_NODES) g_off[idx] = incl - v;
    if (t == 255) g_bsum[b] = incl;
}

__global__ __launch_bounds__(512) void scan_bsum_kernel() {
    __shared__ int sw[16];
    int t = threadIdx.x;
    int v = (t < NB_SCAN) ? g_bsum[t] : 0;
    int lane = t & 31, wid = t >> 5;
    int x = v;
    #pragma unroll
    for (int o = 1; o < 32; o <<= 1) {
        int n = __shfl_up_sync(0xffffffff, x, o);
        if (lane >= o) x += n;
    }
    if (lane == 31) sw[wid] = x;
    __syncthreads();
    if (wid == 0) {
        int s = (lane < 16) ? sw[lane] : 0;
        #pragma unroll
        for (int o = 1; o < 16; o <<= 1) {
            int n = __shfl_up_sync(0xffffffff, s, o);
            if (lane >= o) s += n;
        }
        if (lane < 16) sw[lane] = s;
    }
    __syncthreads();
    int warpoff = (wid > 0) ? sw[wid - 1] : 0;
    int incl = warpoff + x;
    if (t < NB_SCAN) g_boff[t] = incl - v;
    if (t == 511) g_off[N_NODES] = incl;
}

__global__ __launch_bounds__(256) void scan_add_kernel() {
    int idx = blockIdx.x * 256 + threadIdx.x;
    if (idx >= N_NODES) return;
    int o = g_off[idx] + g_boff[blockIdx.x];
    g_off[idx] = o;
    g_cur[idx] = o;
}

__global__ void scatter_kernel(const int* __restrict__ src, const int* __restrict__ dst) {
    int e = blockIdx.x * blockDim.x + threadIdx.x;
    if (e >= N_EDGES) return;
    int p = atomicAdd(&g_cur[dst[e]], 1);
    g_csr[p] = src[e];
}

// ---------------- TF32 tensor-core GEMM ------------------------------------
// TERMS==3: A,B split hi/lo, 3 mma (fp32-class).
// TERMS==2: A split hi/lo, B single rna-tf32, 2 mma (one-operand-tf32 error).
// TERMS==1: both rna-tf32, 1 mma.

__device__ __forceinline__ void cp_async16(void* smem_dst, const void* gmem_src) {
    uint32_t s = (uint32_t)__cvta_generic_to_shared(smem_dst);
    asm volatile("cp.async.cg.shared.global [%0], [%1], 16;\n" :: "r"(s), "l"(gmem_src));
}

__device__ __forceinline__ uint32_t f2tf32(float x) {
    uint32_t r;
    asm("cvt.rna.tf32.f32 %0, %1;\n" : "=r"(r) : "f"(x));
    return r;
}

__device__ __forceinline__ void split_tf32(float v, uint32_t& hi, uint32_t& lo) {
    hi = f2tf32(v);
    lo = f2tf32(v - __uint_as_float(hi));
}

__device__ __forceinline__ void mma_tf32_16x8x8(
    float& c0, float& c1, float& c2, float& c3,
    uint32_t a0, uint32_t a1, uint32_t a2, uint32_t a3,
    uint32_t b0, uint32_t b1)
{
    asm volatile(
        "mma.sync.aligned.m16n8k8.row.col.f32.tf32.tf32.f32 "
        "{%0,%1,%2,%3}, {%4,%5,%6,%7}, {%8,%9}, {%0,%1,%2,%3};\n"
        : "+f"(c0), "+f"(c1), "+f"(c2), "+f"(c3)
        : "r"(a0), "r"(a1), "r"(a2), "r"(a3), "r"(b0), "r"(b1));
}

#define AS_STRIDE 20
#define BS_STRIDE 136

template<int TERMS>
__global__ __launch_bounds__(256) void gemm_tf32_kernel(
    const float* __restrict__ A, const float* __restrict__ B,
    float* __restrict__ C, int M, int N, int K, const float* __restrict__ bias)
{
    __shared__ float As[2][128][AS_STRIDE];
    __shared__ float Bs[2][16][BS_STRIDE];

    const int tid  = threadIdx.x;
    const int warp = tid >> 5;
    const int lane = tid & 31;
    const int g    = lane >> 2;
    const int t    = lane & 3;

    const int rowBase = blockIdx.y * 128;
    const int colBase = blockIdx.x * 128;
    const int mBase = (warp >> 2) * 64;
    const int nBase = (warp & 3) * 32;

    float acc[4][4][4];
    #pragma unroll
    for (int i = 0; i < 4; i++)
        #pragma unroll
        for (int j = 0; j < 4; j++)
            #pragma unroll
            for (int c = 0; c < 4; c++) acc[i][j][c] = 0.0f;

    const int nTiles = K >> 4;

    const int am0 = (tid + 0)   >> 2, aq0 = (tid + 0)   & 3;
    const int am1 = (tid + 256) >> 2, aq1 = (tid + 256) & 3;
    const int bk0 = (tid + 0)   >> 5, bq0 = (tid + 0)   & 31;
    const int bk1 = (tid + 256) >> 5, bq1 = (tid + 256) & 31;

    auto issue_tile = [&](int tIdx, int buf) {
        int k0 = tIdx << 4;
        int ga0 = rowBase + am0;
        int ga1 = rowBase + am1;
        if (ga0 < M) cp_async16(&As[buf][am0][aq0 * 4], A + (size_t)ga0 * K + k0 + aq0 * 4);
        if (ga1 < M) cp_async16(&As[buf][am1][aq1 * 4], A + (size_t)ga1 * K + k0 + aq1 * 4);
        cp_async16(&Bs[buf][bk0][bq0 * 4], B + (size_t)(k0 + bk0) * N + colBase + bq0 * 4);
        cp_async16(&Bs[buf][bk1][bq1 * 4], B + (size_t)(k0 + bk1) * N + colBase + bq1 * 4);
        asm volatile("cp.async.commit_group;\n");
    };

    issue_tile(0, 0);

    for (int tIdx = 0; tIdx < nTiles; tIdx++) {
        int buf = tIdx & 1;
        bool hasNext = (tIdx + 1) < nTiles;
        if (hasNext) issue_tile(tIdx + 1, buf ^ 1);
        if (hasNext) asm volatile("cp.async.wait_group 1;\n");
        else         asm volatile("cp.async.wait_group 0;\n");
        __syncthreads();

        #pragma unroll
        for (int ks = 0; ks < 16; ks += 8) {
            uint32_t ah[4][4], al[4][4];
            #pragma unroll
            for (int mi = 0; mi < 4; mi++) {
                int r = mBase + mi * 16 + g;
                if (TERMS >= 2) {
                    split_tf32(As[buf][r    ][ks + t    ], ah[mi][0], al[mi][0]);
                    split_tf32(As[buf][r + 8][ks + t    ], ah[mi][1], al[mi][1]);
                    split_tf32(As[buf][r    ][ks + t + 4], ah[mi][2], al[mi][2]);
                    split_tf32(As[buf][r + 8][ks + t + 4], ah[mi][3], al[mi][3]);
                } else {
                    ah[mi][0] = f2tf32(As[buf][r    ][ks + t    ]);
                    ah[mi][1] = f2tf32(As[buf][r + 8][ks + t    ]);
                    ah[mi][2] = f2tf32(As[buf][r    ][ks + t + 4]);
                    ah[mi][3] = f2tf32(As[buf][r + 8][ks + t + 4]);
                }
            }
            uint32_t bh[4][2], bl[4][2];
            #pragma unroll
            for (int ni = 0; ni < 4; ni++) {
                int c = nBase + ni * 8 + g;
                if (TERMS == 3) {
                    split_tf32(Bs[buf][ks + t    ][c], bh[ni][0], bl[ni][0]);
                    split_tf32(Bs[buf][ks + t + 4][c], bh[ni][1], bl[ni][1]);
                } else {
                    bh[ni][0] = f2tf32(Bs[buf][ks + t    ][c]);
                    bh[ni][1] = f2tf32(Bs[buf][ks + t + 4][c]);
                }
            }
            #pragma unroll
            for (int mi = 0; mi < 4; mi++)
                #pragma unroll
                for (int ni = 0; ni < 4; ni++) {
                    if (TERMS >= 2)
                        mma_tf32_16x8x8(acc[mi][ni][0], acc[mi][ni][1],
                                        acc[mi][ni][2], acc[mi][ni][3],
                                        al[mi][0], al[mi][1], al[mi][2], al[mi][3],
                                        bh[ni][0], bh[ni][1]);
                    if (TERMS == 3)
                        mma_tf32_16x8x8(acc[mi][ni][0], acc[mi][ni][1],
                                        acc[mi][ni][2], acc[mi][ni][3],
                                        ah[mi][0], ah[mi][1], ah[mi][2], ah[mi][3],
                                        bl[ni][0], bl[ni][1]);
                    mma_tf32_16x8x8(acc[mi][ni][0], acc[mi][ni][1],
                                    acc[mi][ni][2], acc[mi][ni][3],
                                    ah[mi][0], ah[mi][1], ah[mi][2], ah[mi][3],
                                    bh[ni][0], bh[ni][1]);
                }
        }
        __syncthreads();
    }

    #pragma unroll
    for (int mi = 0; mi < 4; mi++) {
        int r0 = rowBase + mBase + mi * 16 + g;
        int r1 = r0 + 8;
        #pragma unroll
        for (int ni = 0; ni < 4; ni++) {
            int c = colBase + nBase + ni * 8 + 2 * t;
            float b0 = 0.f, b1 = 0.f;
            if (bias) { b0 = bias[c]; b1 = bias[c + 1]; }
            if (r0 < M) {
                float2 v = make_float2(acc[mi][ni][0] + b0, acc[mi][ni][1] + b1);
                *(float2*)(C + (size_t)r0 * N + c) = v;
            }
            if (r1 < M) {
                float2 v = make_float2(acc[mi][ni][2] + b0, acc[mi][ni][3] + b1);
                *(float2*)(C + (size_t)r1 * N + c) = v;
            }
        }
    }
}

// ---------------- aggregation: warp per node, 8-deep MLP --------------------
// layer 1: h1 = relu( mean_j t[j,0:128] + b_l1 + t[i,128:256] )
__global__ __launch_bounds__(256) void agg1_kernel(const float* __restrict__ b_l1) {
    int node = (blockIdx.x * blockDim.x + threadIdx.x) >> 5;
    int lane = threadIdx.x & 31;
    if (node >= N_NODES) return;
    int s = g_off[node], e = g_off[node + 1];
    float4 a0 = make_float4(0.f, 0.f, 0.f, 0.f);
    float4 a1 = make_float4(0.f, 0.f, 0.f, 0.f);
    int i = s;
    for (; i + 7 < e; i += 8) {
        int sj[8];
        #pragma unroll
        for (int u = 0; u < 8; u++) sj[u] = g_csr[i + u];
        float4 v[8];
        #pragma unroll
        for (int u = 0; u < 8; u++)
            v[u] = *(const float4*)(g_t + (size_t)sj[u] * 256 + lane * 4);
        #pragma unroll
        for (int u = 0; u < 4; u++) {
            a0.x += v[u].x; a0.y += v[u].y; a0.z += v[u].z; a0.w += v[u].w;
        }
        #pragma unroll
        for (int u = 4; u < 8; u++) {
            a1.x += v[u].x; a1.y += v[u].y; a1.z += v[u].z; a1.w += v[u].w;
        }
    }
    for (; i < e; i++) {
        int s0 = g_csr[i];
        float4 v0 = *(const float4*)(g_t + (size_t)s0 * 256 + lane * 4);
        a0.x += v0.x; a0.y += v0.y; a0.z += v0.z; a0.w += v0.w;
    }
    float inv = 1.0f / fmaxf((float)(e - s), 1.0f);
    float4 r  = *(const float4*)(g_t + (size_t)node * 256 + 128 + lane * 4);
    float4 bb = *(const float4*)(b_l1 + lane * 4);
    float4 o;
    o.x = fmaxf((a0.x + a1.x) * inv + bb.x + r.x, 0.f);
    o.y = fmaxf((a0.y + a1.y) * inv + bb.y + r.y, 0.f);
    o.z = fmaxf((a0.z + a1.z) * inv + bb.z + r.z, 0.f);
    o.w = fmaxf((a0.w + a1.w) * inv + bb.w + r.w, 0.f);
    *(float4*)(g_h1 + (size_t)node * HID + lane * 4) = o;
}

// layer 2 aggregation FUSED with folded decoder:
//   m = mean_j h1[j]; o = h1[i]
//   s_a[i] = m . w2a[0:128] + o . w2a[128:256] + (b_l2 . wa)
//   s_b[i] = m . w2b[0:128] + o . w2b[128:256] + (b_l2 . wb)
__global__ __launch_bounds__(256) void agg2_sab_kernel() {
    int node = (blockIdx.x * blockDim.x + threadIdx.x) >> 5;
    int lane = threadIdx.x & 31;
    if (node >= N_NODES) return;
    int s = g_off[node], e = g_off[node + 1];
    float4 a0 = make_float4(0.f, 0.f, 0.f, 0.f);
    float4 a1 = make_float4(0.f, 0.f, 0.f, 0.f);
    int i = s;
    for (; i + 7 < e; i += 8) {
        int sj[8];
        #pragma unroll
        for (int u = 0; u < 8; u++) sj[u] = g_csr[i + u];
        float4 v[8];
        #pragma unroll
        for (int u = 0; u < 8; u++)
            v[u] = *(const float4*)(g_h1 + (size_t)sj[u] * HID + lane * 4);
        #pragma unroll
        for (int u = 0; u < 4; u++) {
            a0.x += v[u].x; a0.y += v[u].y; a0.z += v[u].z; a0.w += v[u].w;
        }
        #pragma unroll
        for (int u = 4; u < 8; u++) {
            a1.x += v[u].x; a1.y += v[u].y; a1.z += v[u].z; a1.w += v[u].w;
        }
    }
    for (; i < e; i++) {
        int s0 = g_csr[i];
        float4 v0 = *(const float4*)(g_h1 + (size_t)s0 * HID + lane * 4);
        a0.x += v0.x; a0.y += v0.y; a0.z += v0.z; a0.w += v0.w;
    }
    float inv = 1.0f / fmaxf((float)(e - s), 1.0f);
    float4 m;
    m.x = (a0.x + a1.x) * inv;
    m.y = (a0.y + a1.y) * inv;
    m.z = (a0.z + a1.z) * inv;
    m.w = (a0.w + a1.w) * inv;
    float4 o = *(const float4*)(g_h1 + (size_t)node * HID + lane * 4);

    float4 wa0 = *(const float4*)(g_w2a + lane * 4);
    float4 wa1 = *(const float4*)(g_w2a + 128 + lane * 4);
    float4 wb0 = *(const float4*)(g_w2b + lane * 4);
    float4 wb1 = *(const float4*)(g_w2b + 128 + lane * 4);

    float da = m.x * wa0.x + m.y * wa0.y + m.z * wa0.z + m.w * wa0.w
             + o.x * wa1.x + o.y * wa1.y + o.z * wa1.z + o.w * wa1.w;
    float db = m.x * wb0.x + m.y * wb0.y + m.z * wb0.z + m.w * wb0.w
             + o.x * wb1.x + o.y * wb1.y + o.z * wb1.z + o.w * wb1.w;
    #pragma unroll
    for (int off = 16; off > 0; off >>= 1) {
        da += __shfl_xor_sync(0xffffffff, da, off);
        db += __shfl_xor_sync(0xffffffff, db, off);
    }
    if (lane == 0) {
        g_sa[node] = da + g_c[0];
        g_sb[node] = db + g_c[1];
    }
}

__global__ void score_kernel(const int* __restrict__ pos, const int* __restrict__ neg,
                             const float* __restrict__ b_lin, float* __restrict__ out)
{
    int idx = blockIdx.x * blockDim.x + threadIdx.x;
    if (idx >= 1000000) return;
    float b = b_lin[0];
    if (idx < 500000) {
        int s = pos[idx];
        int d = pos[500000 + idx];
        out[idx] = g_sa[s] + g_sb[d] + b;
    } else {
        int e = idx - 500000;
        int s = neg[e];
        int d = neg[500000 + e];
        out[idx] = g_sa[s] + g_sb[d] + b;
    }
}

// ---------------- launch ----------------------------------------------------
extern "C" void kernel_launch(void* const* d_in, const int* in_sizes, int n_in,
                              void* d_out, int out_size)
{
    const float* x     = (const float*)d_in[0];
    const int*   ei    = (const int*)  d_in[1];
    const int*   pos   = (const int*)  d_in[2];
    const int*   neg   = (const int*)  d_in[3];
    const float* W_l1  = (const float*)d_in[4];
    const float* b_l1  = (const float*)d_in[5];
    const float* W_r1  = (const float*)d_in[6];
    const float* W_l2  = (const float*)d_in[7];
    const float* b_l2  = (const float*)d_in[8];
    const float* W_r2  = (const float*)d_in[9];
    const float* W_lin = (const float*)d_in[10];
    const float* b_lin = (const float*)d_in[11];
    float*       out   = (float*)d_out;

    const int* e_src = ei;
    const int* e_dst = ei + N_EDGES;

    void *p_t, *p_W1;
    cudaGetSymbolAddress(&p_t,  g_t);
    cudaGetSymbolAddress(&p_W1, g_W1);

    // CSR build
    zero_cnt_kernel<<<(N_NODES + 255) / 256, 256>>>();
    hist_kernel<<<(N_EDGES + 255) / 256, 256>>>(e_dst);
    scan_local_kernel<<<NB_SCAN, 256>>>();
    scan_bsum_kernel<<<1, 512>>>();
    scan_add_kernel<<<NB_SCAN, 256>>>();
    scatter_kernel<<<(N_EDGES + 255) / 256, 256>>>(e_src, e_dst);

    // weight prep
    pack_w1_kernel<<<(IN_DIM * 256 + 255) / 256, 256>>>(W_l1, W_r1);
    decoder_pre_kernel<<<1, 256>>>(W_l2, W_r2, b_l2, W_lin);

    // layer 1: t = x @ [W_l1 | W_r1]   (100000 x 384) @ (384 x 256), 2-term tf32
    {
        dim3 grid(256 / 128, (N_NODES + 127) / 128);
        gemm_tf32_kernel<2><<<grid, 256>>>(x, (const float*)p_W1, (float*)p_t,
                                           N_NODES, 256, IN_DIM, nullptr);
    }
    // h1 = relu(mean-aggregate + b + root)
    agg1_kernel<<<(N_NODES * 32 + 255) / 256, 256>>>(b_l1);

    // layer 2 + decoder fused: s_a/s_b directly from h1 aggregation
    agg2_sab_kernel<<<(N_NODES * 32 + 255) / 256, 256>>>();

    // final scoring
    score_kernel<<<(1000000 + 255) / 256, 256>>>(pos, neg, b_lin, out);
}

// round 13
// speedup vs baseline: 2.1300x; 1.1715x over previous
#include <cuda_runtime.h>
#include <cuda_fp16.h>
#include <cstdint>

#define N_NODES 100000
#define N_EDGES 3200000
#define IN_DIM  384
#define HID     128
#define NB_SCAN ((N_NODES + 255) / 256)   // 391 scan blocks

// ---------------- scratch (device globals; no allocation allowed) ----------
__device__ int    g_cnt[N_NODES];
__device__ int    g_off[N_NODES + 1];
__device__ int    g_cur[N_NODES];
__device__ int    g_csr[N_EDGES];
__device__ int    g_bsum[512];
__device__ int    g_boff[512];
__device__ __half g_tlh[(size_t)N_NODES * HID];   // x@W_l1 in fp16 (gather operand, layer 1)
__device__ float  g_tr [(size_t)N_NODES * HID];   // x@W_r1 in fp32 (own/root term)
__device__ float  g_h1 [(size_t)N_NODES * HID];   // h1 fp32 (own term, layer 2)
__device__ __half g_h1h[(size_t)N_NODES * HID];   // h1 fp16 (gather operand, layer 2)
__device__ float  g_sa [N_NODES];
__device__ float  g_sb [N_NODES];
__device__ float  g_W1 [IN_DIM * 256];            // [W_l1 | W_r1]  (384 x 256)
__device__ float  g_w2a[256];                     // W2 @ wa (decoder-folded layer-2 weights)
__device__ float  g_w2b[256];                     // W2 @ wb
__device__ float  g_c  [2];                       // b_l2 . wa, b_l2 . wb

// ---------------- small utility kernels ------------------------------------
__global__ void zero_cnt_kernel() {
    int i = blockIdx.x * blockDim.x + threadIdx.x;
    if (i < N_NODES) g_cnt[i] = 0;
}

__global__ void pack_w1_kernel(const float* __restrict__ Wl, const float* __restrict__ Wr) {
    int idx = blockIdx.x * blockDim.x + threadIdx.x;
    if (idx >= IN_DIM * 256) return;
    int k = idx >> 8;
    int j = idx & 255;
    g_W1[idx] = (j < HID) ? Wl[k * HID + j] : Wr[k * HID + (j - HID)];
}

// decoder fold: w2a[k] = sum_j W2[k][j]*W_lin[j],  w2b[k] = sum_j W2[k][j]*W_lin[128+j]
__global__ void decoder_pre_kernel(const float* __restrict__ Wl2, const float* __restrict__ Wr2,
                                   const float* __restrict__ b_l2, const float* __restrict__ W_lin)
{
    int k = blockIdx.x * blockDim.x + threadIdx.x;
    if (k >= 256) return;
    const float* row = (k < HID) ? (Wl2 + (size_t)k * HID) : (Wr2 + (size_t)(k - HID) * HID);
    float sa = 0.f, sb = 0.f;
    for (int j = 0; j < HID; j++) {
        float w = row[j];
        sa += w * W_lin[j];
        sb += w * W_lin[HID + j];
    }
    g_w2a[k] = sa;
    g_w2b[k] = sb;
    if (k == 0) {
        float ca = 0.f, cb = 0.f;
        for (int j = 0; j < HID; j++) {
            ca += b_l2[j] * W_lin[j];
            cb += b_l2[j] * W_lin[HID + j];
        }
        g_c[0] = ca;
        g_c[1] = cb;
    }
}

__global__ void hist_kernel(const int* __restrict__ dst) {
    int e = blockIdx.x * blockDim.x + threadIdx.x;
    if (e < N_EDGES) atomicAdd(&g_cnt[dst[e]], 1);
}

// ---------------- 3-kernel decoupled exclusive scan -------------------------
__global__ __launch_bounds__(256) void scan_local_kernel() {
    __shared__ int sw[8];
    int b = blockIdx.x, t = threadIdx.x;
    int idx = b * 256 + t;
    int v = (idx < N_NODES) ? g_cnt[idx] : 0;
    int lane = t & 31, wid = t >> 5;
    int x = v;
    #pragma unroll
    for (int o = 1; o < 32; o <<= 1) {
        int n = __shfl_up_sync(0xffffffff, x, o);
        if (lane >= o) x += n;
    }
    if (lane == 31) sw[wid] = x;
    __syncthreads();
    if (wid == 0) {
        int s = (lane < 8) ? sw[lane] : 0;
        #pragma unroll
        for (int o = 1; o < 8; o <<= 1) {
            int n = __shfl_up_sync(0xffffffff, s, o);
            if (lane >= o) s += n;
        }
        if (lane < 8) sw[lane] = s;
    }
    __syncthreads();
    int warpoff = (wid > 0) ? sw[wid - 1] : 0;
    int incl = warpoff + x;
    if (idx < N_NODES) g_off[idx] = incl - v;
    if (t == 255) g_bsum[b] = incl;
}

__global__ __launch_bounds__(512) void scan_bsum_kernel() {
    __shared__ int sw[16];
    int t = threadIdx.x;
    int v = (t < NB_SCAN) ? g_bsum[t] : 0;
    int lane = t & 31, wid = t >> 5;
    int x = v;
    #pragma unroll
    for (int o = 1; o < 32; o <<= 1) {
        int n = __shfl_up_sync(0xffffffff, x, o);
        if (lane >= o) x += n;
    }
    if (lane == 31) sw[wid] = x;
    __syncthreads();
    if (wid == 0) {
        int s = (lane < 16) ? sw[lane] : 0;
        #pragma unroll
        for (int o = 1; o < 16; o <<= 1) {
            int n = __shfl_up_sync(0xffffffff, s, o);
            if (lane >= o) s += n;
        }
        if (lane < 16) sw[lane] = s;
    }
    __syncthreads();
    int warpoff = (wid > 0) ? sw[wid - 1] : 0;
    int incl = warpoff + x;
    if (t < NB_SCAN) g_boff[t] = incl - v;
    if (t == 511) g_off[N_NODES] = incl;
}

__global__ __launch_bounds__(256) void scan_add_kernel() {
    int idx = blockIdx.x * 256 + threadIdx.x;
    if (idx >= N_NODES) return;
    int o = g_off[idx] + g_boff[blockIdx.x];
    g_off[idx] = o;
    g_cur[idx] = o;
}

__global__ void scatter_kernel(const int* __restrict__ src, const int* __restrict__ dst) {
    int e = blockIdx.x * blockDim.x + threadIdx.x;
    if (e >= N_EDGES) return;
    int p = atomicAdd(&g_cur[dst[e]], 1);
    g_csr[p] = src[e];
}

// ---------------- TF32 tensor-core GEMM (2-term), split epilogue ------------
// C[M,256] = A[M,K] @ B[K,256]. blockIdx.x==0 -> cols [0,128) to Cl (fp16);
// blockIdx.x==1 -> cols [128,256) to Cr (fp32, col-128 rebased).

__device__ __forceinline__ void cp_async16(void* smem_dst, const void* gmem_src) {
    uint32_t s = (uint32_t)__cvta_generic_to_shared(smem_dst);
    asm volatile("cp.async.cg.shared.global [%0], [%1], 16;\n" :: "r"(s), "l"(gmem_src));
}

__device__ __forceinline__ uint32_t f2tf32(float x) {
    uint32_t r;
    asm("cvt.rna.tf32.f32 %0, %1;\n" : "=r"(r) : "f"(x));
    return r;
}

__device__ __forceinline__ void split_tf32(float v, uint32_t& hi, uint32_t& lo) {
    hi = f2tf32(v);
    lo = f2tf32(v - __uint_as_float(hi));
}

__device__ __forceinline__ void mma_tf32_16x8x8(
    float& c0, float& c1, float& c2, float& c3,
    uint32_t a0, uint32_t a1, uint32_t a2, uint32_t a3,
    uint32_t b0, uint32_t b1)
{
    asm volatile(
        "mma.sync.aligned.m16n8k8.row.col.f32.tf32.tf32.f32 "
        "{%0,%1,%2,%3}, {%4,%5,%6,%7}, {%8,%9}, {%0,%1,%2,%3};\n"
        : "+f"(c0), "+f"(c1), "+f"(c2), "+f"(c3)
        : "r"(a0), "r"(a1), "r"(a2), "r"(a3), "r"(b0), "r"(b1));
}

#define AS_STRIDE 20
#define BS_STRIDE 136

__global__ __launch_bounds__(256) void gemm1_tf32_kernel(
    const float* __restrict__ A, const float* __restrict__ B,
    __half* __restrict__ Cl, float* __restrict__ Cr, int M, int K)
{
    const int N = 256;
    __shared__ float As[2][128][AS_STRIDE];
    __shared__ float Bs[2][16][BS_STRIDE];

    const int tid  = threadIdx.x;
    const int warp = tid >> 5;
    const int lane = tid & 31;
    const int g    = lane >> 2;
    const int t    = lane & 3;

    const int rowBase = blockIdx.y * 128;
    const int colBase = blockIdx.x * 128;
    const int mBase = (warp >> 2) * 64;
    const int nBase = (warp & 3) * 32;

    float acc[4][4][4];
    #pragma unroll
    for (int i = 0; i < 4; i++)
        #pragma unroll
        for (int j = 0; j < 4; j++)
            #pragma unroll
            for (int c = 0; c < 4; c++) acc[i][j][c] = 0.0f;

    const int nTiles = K >> 4;

    const int am0 = (tid + 0)   >> 2, aq0 = (tid + 0)   & 3;
    const int am1 = (tid + 256) >> 2, aq1 = (tid + 256) & 3;
    const int bk0 = (tid + 0)   >> 5, bq0 = (tid + 0)   & 31;
    const int bk1 = (tid + 256) >> 5, bq1 = (tid + 256) & 31;

    auto issue_tile = [&](int tIdx, int buf) {
        int k0 = tIdx << 4;
        int ga0 = rowBase + am0;
        int ga1 = rowBase + am1;
        if (ga0 < M) cp_async16(&As[buf][am0][aq0 * 4], A + (size_t)ga0 * K + k0 + aq0 * 4);
        if (ga1 < M) cp_async16(&As[buf][am1][aq1 * 4], A + (size_t)ga1 * K + k0 + aq1 * 4);
        cp_async16(&Bs[buf][bk0][bq0 * 4], B + (size_t)(k0 + bk0) * N + colBase + bq0 * 4);
        cp_async16(&Bs[buf][bk1][bq1 * 4], B + (size_t)(k0 + bk1) * N + colBase + bq1 * 4);
        asm volatile("cp.async.commit_group;\n");
    };

    issue_tile(0, 0);

    for (int tIdx = 0; tIdx < nTiles; tIdx++) {
        int buf = tIdx & 1;
        bool hasNext = (tIdx + 1) < nTiles;
        if (hasNext) issue_tile(tIdx + 1, buf ^ 1);
        if (hasNext) asm volatile("cp.async.wait_group 1;\n");
        else         asm volatile("cp.async.wait_group 0;\n");
        __syncthreads();

        #pragma unroll
        for (int ks = 0; ks < 16; ks += 8) {
            uint32_t ah[4][4], al[4][4];
            #pragma unroll
            for (int mi = 0; mi < 4; mi++) {
                int r = mBase + mi * 16 + g;
                split_tf32(As[buf][r    ][ks + t    ], ah[mi][0], al[mi][0]);
                split_tf32(As[buf][r + 8][ks + t    ], ah[mi][1], al[mi][1]);
                split_tf32(As[buf][r    ][ks + t + 4], ah[mi][2], al[mi][2]);
                split_tf32(As[buf][r + 8][ks + t + 4], ah[mi][3], al[mi][3]);
            }
            uint32_t bh[4][2];
            #pragma unroll
            for (int ni = 0; ni < 4; ni++) {
                int c = nBase + ni * 8 + g;
                bh[ni][0] = f2tf32(Bs[buf][ks + t    ][c]);
                bh[ni][1] = f2tf32(Bs[buf][ks + t + 4][c]);
            }
            #pragma unroll
            for (int mi = 0; mi < 4; mi++)
                #pragma unroll
                for (int ni = 0; ni < 4; ni++) {
                    mma_tf32_16x8x8(acc[mi][ni][0], acc[mi][ni][1],
                                    acc[mi][ni][2], acc[mi][ni][3],
                                    al[mi][0], al[mi][1], al[mi][2], al[mi][3],
                                    bh[ni][0], bh[ni][1]);
                    mma_tf32_16x8x8(acc[mi][ni][0], acc[mi][ni][1],
                                    acc[mi][ni][2], acc[mi][ni][3],
                                    ah[mi][0], ah[mi][1], ah[mi][2], ah[mi][3],
                                    bh[ni][0], bh[ni][1]);
                }
        }
        __syncthreads();
    }

    // split epilogue
    #pragma unroll
    for (int mi = 0; mi < 4; mi++) {
        int r0 = rowBase + mBase + mi * 16 + g;
        int r1 = r0 + 8;
        #pragma unroll
        for (int ni = 0; ni < 4; ni++) {
            int c = colBase + nBase + ni * 8 + 2 * t;
            if (colBase == 0) {
                // fp16 gather operand
                if (r0 < M) {
                    __half2 v = __floats2half2_rn(acc[mi][ni][0], acc[mi][ni][1]);
                    *(__half2*)(Cl + (size_t)r0 * HID + c) = v;
                }
                if (r1 < M) {
                    __half2 v = __floats2half2_rn(acc[mi][ni][2], acc[mi][ni][3]);
                    *(__half2*)(Cl + (size_t)r1 * HID + c) = v;
                }
            } else {
                int cr = c - 128;
                if (r0 < M) {
                    float2 v = make_float2(acc[mi][ni][0], acc[mi][ni][1]);
                    *(float2*)(Cr + (size_t)r0 * HID + cr) = v;
                }
                if (r1 < M) {
                    float2 v = make_float2(acc[mi][ni][2], acc[mi][ni][3]);
                    *(float2*)(Cr + (size_t)r1 * HID + cr) = v;
                }
            }
        }
    }
}

// ---------------- aggregation: warp per node, fp16 gather -------------------
__device__ __forceinline__ void acc_half4(float4& a, uint2 raw) {
    __half2 h0 = *reinterpret_cast<__half2*>(&raw.x);
    __half2 h1 = *reinterpret_cast<__half2*>(&raw.y);
    float2 f0 = __half22float2(h0);
    float2 f1 = __half22float2(h1);
    a.x += f0.x; a.y += f0.y; a.z += f1.x; a.w += f1.y;
}

// layer 1: h1 = relu( mean_j tl[j] + b_l1 + tr[i] ); write fp32 + fp16 copies
__global__ __launch_bounds__(256) void agg1_kernel(const float* __restrict__ b_l1) {
    int node = (blockIdx.x * blockDim.x + threadIdx.x) >> 5;
    int lane = threadIdx.x & 31;
    if (node >= N_NODES) return;
    int s = g_off[node], e = g_off[node + 1];
    float4 a0 = make_float4(0.f, 0.f, 0.f, 0.f);
    float4 a1 = make_float4(0.f, 0.f, 0.f, 0.f);
    int i = s;
    for (; i + 7 < e; i += 8) {
        int sj[8];
        #pragma unroll
        for (int u = 0; u < 8; u++) sj[u] = g_csr[i + u];
        uint2 v[8];
        #pragma unroll
        for (int u = 0; u < 8; u++)
            v[u] = *(const uint2*)(g_tlh + (size_t)sj[u] * HID + lane * 4);
        #pragma unroll
        for (int u = 0; u < 4; u++) acc_half4(a0, v[u]);
        #pragma unroll
        for (int u = 4; u < 8; u++) acc_half4(a1, v[u]);
    }
    for (; i < e; i++) {
        int s0 = g_csr[i];
        uint2 v0 = *(const uint2*)(g_tlh + (size_t)s0 * HID + lane * 4);
        acc_half4(a0, v0);
    }
    float inv = 1.0f / fmaxf((float)(e - s), 1.0f);
    float4 r  = *(const float4*)(g_tr + (size_t)node * HID + lane * 4);
    float4 bb = *(const float4*)(b_l1 + lane * 4);
    float4 o;
    o.x = fmaxf((a0.x + a1.x) * inv + bb.x + r.x, 0.f);
    o.y = fmaxf((a0.y + a1.y) * inv + bb.y + r.y, 0.f);
    o.z = fmaxf((a0.z + a1.z) * inv + bb.z + r.z, 0.f);
    o.w = fmaxf((a0.w + a1.w) * inv + bb.w + r.w, 0.f);
    *(float4*)(g_h1 + (size_t)node * HID + lane * 4) = o;
    uint2 packed;
    __half2 p0 = __floats2half2_rn(o.x, o.y);
    __half2 p1 = __floats2half2_rn(o.z, o.w);
    packed.x = *reinterpret_cast<uint32_t*>(&p0);
    packed.y = *reinterpret_cast<uint32_t*>(&p1);
    *(uint2*)(g_h1h + (size_t)node * HID + lane * 4) = packed;
}

// layer 2 aggregation FUSED with folded decoder (fp16 gather, fp32 own)
__global__ __launch_bounds__(256) void agg2_sab_kernel() {
    int node = (blockIdx.x * blockDim.x + threadIdx.x) >> 5;
    int lane = threadIdx.x & 31;
    if (node >= N_NODES) return;
    int s = g_off[node], e = g_off[node + 1];
    float4 a0 = make_float4(0.f, 0.f, 0.f, 0.f);
    float4 a1 = make_float4(0.f, 0.f, 0.f, 0.f);
    int i = s;
    for (; i + 7 < e; i += 8) {
        int sj[8];
        #pragma unroll
        for (int u = 0; u < 8; u++) sj[u] = g_csr[i + u];
        uint2 v[8];
        #pragma unroll
        for (int u = 0; u < 8; u++)
            v[u] = *(const uint2*)(g_h1h + (size_t)sj[u] * HID + lane * 4);
        #pragma unroll
        for (int u = 0; u < 4; u++) acc_half4(a0, v[u]);
        #pragma unroll
        for (int u = 4; u < 8; u++) acc_half4(a1, v[u]);
    }
    for (; i < e; i++) {
        int s0 = g_csr[i];
        uint2 v0 = *(const uint2*)(g_h1h + (size_t)s0 * HID + lane * 4);
        acc_half4(a0, v0);
    }
    float inv = 1.0f / fmaxf((float)(e - s), 1.0f);
    float4 m;
    m.x = (a0.x + a1.x) * inv;
    m.y = (a0.y + a1.y) * inv;
    m.z = (a0.z + a1.z) * inv;
    m.w = (a0.w + a1.w) * inv;
    float4 o = *(const float4*)(g_h1 + (size_t)node * HID + lane * 4);

    float4 wa0 = *(const float4*)(g_w2a + lane * 4);
    float4 wa1 = *(const float4*)(g_w2a + 128 + lane * 4);
    float4 wb0 = *(const float4*)(g_w2b + lane * 4);
    float4 wb1 = *(const float4*)(g_w2b + 128 + lane * 4);

    float da = m.x * wa0.x + m.y * wa0.y + m.z * wa0.z + m.w * wa0.w
             + o.x * wa1.x + o.y * wa1.y + o.z * wa1.z + o.w * wa1.w;
    float db = m.x * wb0.x + m.y * wb0.y + m.z * wb0.z + m.w * wb0.w
             + o.x * wb1.x + o.y * wb1.y + o.z * wb1.z + o.w * wb1.w;
    #pragma unroll
    for (int off = 16; off > 0; off >>= 1) {
        da += __shfl_xor_sync(0xffffffff, da, off);
        db += __shfl_xor_sync(0xffffffff, db, off);
    }
    if (lane == 0) {
        g_sa[node] = da + g_c[0];
        g_sb[node] = db + g_c[1];
    }
}

__global__ void score_kernel(const int* __restrict__ pos, const int* __restrict__ neg,
                             const float* __restrict__ b_lin, float* __restrict__ out)
{
    int idx = blockIdx.x * blockDim.x + threadIdx.x;
    if (idx >= 1000000) return;
    float b = b_lin[0];
    if (idx < 500000) {
        int s = pos[idx];
        int d = pos[500000 + idx];
        out[idx] = g_sa[s] + g_sb[d] + b;
    } else {
        int e = idx - 500000;
        int s = neg[e];
        int d = neg[500000 + e];
        out[idx] = g_sa[s] + g_sb[d] + b;
    }
}

// ---------------- launch ----------------------------------------------------
extern "C" void kernel_launch(void* const* d_in, const int* in_sizes, int n_in,
                              void* d_out, int out_size)
{
    const float* x     = (const float*)d_in[0];
    const int*   ei    = (const int*)  d_in[1];
    const int*   pos   = (const int*)  d_in[2];
    const int*   neg   = (const int*)  d_in[3];
    const float* W_l1  = (const float*)d_in[4];
    const float* b_l1  = (const float*)d_in[5];
    const float* W_r1  = (const float*)d_in[6];
    const float* W_l2  = (const float*)d_in[7];
    const float* b_l2  = (const float*)d_in[8];
    const float* W_r2  = (const float*)d_in[9];
    const float* W_lin = (const float*)d_in[10];
    const float* b_lin = (const float*)d_in[11];
    float*       out   = (float*)d_out;

    const int* e_src = ei;
    const int* e_dst = ei + N_EDGES;

    void *p_tlh, *p_tr, *p_W1;
    cudaGetSymbolAddress(&p_tlh, g_tlh);
    cudaGetSymbolAddress(&p_tr,  g_tr);
    cudaGetSymbolAddress(&p_W1,  g_W1);

    // CSR build
    zero_cnt_kernel<<<(N_NODES + 255) / 256, 256>>>();
    hist_kernel<<<(N_EDGES + 255) / 256, 256>>>(e_dst);
    scan_local_kernel<<<NB_SCAN, 256>>>();
    scan_bsum_kernel<<<1, 512>>>();
    scan_add_kernel<<<NB_SCAN, 256>>>();
    scatter_kernel<<<(N_EDGES + 255) / 256, 256>>>(e_src, e_dst);

    // weight prep
    pack_w1_kernel<<<(IN_DIM * 256 + 255) / 256, 256>>>(W_l1, W_r1);
    decoder_pre_kernel<<<1, 256>>>(W_l2, W_r2, b_l2, W_lin);

    // layer 1 GEMM: tl (fp16) | tr (fp32) = x @ [W_l1 | W_r1], 2-term tf32
    {
        dim3 grid(2, (N_NODES + 127) / 128);
        gemm1_tf32_kernel<<<grid, 256>>>(x, (const float*)p_W1,
                                         (__half*)p_tlh, (float*)p_tr,
                                         N_NODES, IN_DIM);
    }
    // h1 = relu(mean-aggregate + b + root)
    agg1_kernel<<<(N_NODES * 32 + 255) / 256, 256>>>(b_l1);

    // layer 2 + decoder fused
    agg2_sab_kernel<<<(N_NODES * 32 + 255) / 256, 256>>>();

    // final scoring
    score_kernel<<<(1000000 + 255) / 256, 256>>>(pos, neg, b_lin, out);
}

// round 16
// speedup vs baseline: 2.1574x; 1.0129x over previous
#include <cuda_runtime.h>
#include <cuda_fp16.h>
#include <cstdint>

#define N_NODES 100000
#define N_EDGES 3200000
#define IN_DIM  384
#define HID     128
#define NB_SCAN ((N_NODES + 255) / 256)   // 391 scan blocks

// ---------------- scratch (device globals; no allocation allowed) ----------
__device__ int    g_cnt[N_NODES];
__device__ int    g_off[N_NODES + 1];
__device__ int    g_cur[N_NODES];
__device__ int    g_csr[N_EDGES];
__device__ int    g_bsum[512];
__device__ int    g_boff[512];
__device__ __half g_tlh[(size_t)N_NODES * HID];   // x@W_l1 in fp16 (gather operand, layer 1)
__device__ float  g_tr [(size_t)N_NODES * HID];   // x@W_r1 in fp32 (own/root term)
__device__ float  g_h1 [(size_t)N_NODES * HID];   // h1 fp32 (own term, layer 2)
__device__ __half g_h1h[(size_t)N_NODES * HID];   // h1 fp16 (gather operand, layer 2)
__device__ float  g_sa [N_NODES];
__device__ float  g_sb [N_NODES];
__device__ float  g_W1 [IN_DIM * 256];            // [W_l1 | W_r1]  (384 x 256)
__device__ float  g_w2a[256];                     // W2 @ wa (decoder-folded layer-2 weights)
__device__ float  g_w2b[256];                     // W2 @ wb
__device__ float  g_c  [2];                       // b_l2 . wa, b_l2 . wb

// ---------------- small utility kernels ------------------------------------
__global__ void zero_cnt_kernel() {
    int i = blockIdx.x * blockDim.x + threadIdx.x;
    if (i < N_NODES) g_cnt[i] = 0;
}

__global__ void pack_w1_kernel(const float* __restrict__ Wl, const float* __restrict__ Wr) {
    int idx = blockIdx.x * blockDim.x + threadIdx.x;
    if (idx >= IN_DIM * 256) return;
    int k = idx >> 8;
    int j = idx & 255;
    g_W1[idx] = (j < HID) ? Wl[k * HID + j] : Wr[k * HID + (j - HID)];
}

// decoder fold: w2a[k] = sum_j W2[k][j]*W_lin[j],  w2b[k] = sum_j W2[k][j]*W_lin[128+j]
__global__ void decoder_pre_kernel(const float* __restrict__ Wl2, const float* __restrict__ Wr2,
                                   const float* __restrict__ b_l2, const float* __restrict__ W_lin)
{
    int k = blockIdx.x * blockDim.x + threadIdx.x;
    if (k >= 256) return;
    const float* row = (k < HID) ? (Wl2 + (size_t)k * HID) : (Wr2 + (size_t)(k - HID) * HID);
    float sa = 0.f, sb = 0.f;
    for (int j = 0; j < HID; j++) {
        float w = row[j];
        sa += w * W_lin[j];
        sb += w * W_lin[HID + j];
    }
    g_w2a[k] = sa;
    g_w2b[k] = sb;
    if (k == 0) {
        float ca = 0.f, cb = 0.f;
        for (int j = 0; j < HID; j++) {
            ca += b_l2[j] * W_lin[j];
            cb += b_l2[j] * W_lin[HID + j];
        }
        g_c[0] = ca;
        g_c[1] = cb;
    }
}

__global__ void hist_kernel(const int* __restrict__ dst) {
    int e = blockIdx.x * blockDim.x + threadIdx.x;
    if (e < N_EDGES) atomicAdd(&g_cnt[dst[e]], 1);
}

// ---------------- 3-kernel decoupled exclusive scan -------------------------
__global__ __launch_bounds__(256) void scan_local_kernel() {
    __shared__ int sw[8];
    int b = blockIdx.x, t = threadIdx.x;
    int idx = b * 256 + t;
    int v = (idx < N_NODES) ? g_cnt[idx] : 0;
    int lane = t & 31, wid = t >> 5;
    int x = v;
    #pragma unroll
    for (int o = 1; o < 32; o <<= 1) {
        int n = __shfl_up_sync(0xffffffff, x, o);
        if (lane >= o) x += n;
    }
    if (lane == 31) sw[wid] = x;
    __syncthreads();
    if (wid == 0) {
        int s = (lane < 8) ? sw[lane] : 0;
        #pragma unroll
        for (int o = 1; o < 8; o <<= 1) {
            int n = __shfl_up_sync(0xffffffff, s, o);
            if (lane >= o) s += n;
        }
        if (lane < 8) sw[lane] = s;
    }
    __syncthreads();
    int warpoff = (wid > 0) ? sw[wid - 1] : 0;
    int incl = warpoff + x;
    if (idx < N_NODES) g_off[idx] = incl - v;
    if (t == 255) g_bsum[b] = incl;
}

__global__ __launch_bounds__(512) void scan_bsum_kernel() {
    __shared__ int sw[16];
    int t = threadIdx.x;
    int v = (t < NB_SCAN) ? g_bsum[t] : 0;
    int lane = t & 31, wid = t >> 5;
    int x = v;
    #pragma unroll
    for (int o = 1; o < 32; o <<= 1) {
        int n = __shfl_up_sync(0xffffffff, x, o);
        if (lane >= o) x += n;
    }
    if (lane == 31) sw[wid] = x;
    __syncthreads();
    if (wid == 0) {
        int s = (lane < 16) ? sw[lane] : 0;
        #pragma unroll
        for (int o = 1; o < 16; o <<= 1) {
            int n = __shfl_up_sync(0xffffffff, s, o);
            if (lane >= o) s += n;
        }
        if (lane < 16) sw[lane] = s;
    }
    __syncthreads();
    int warpoff = (wid > 0) ? sw[wid - 1] : 0;
    int incl = warpoff + x;
    if (t < NB_SCAN) g_boff[t] = incl - v;
    if (t == 511) g_off[N_NODES] = incl;
}

__global__ __launch_bounds__(256) void scan_add_kernel() {
    int idx = blockIdx.x * 256 + threadIdx.x;
    if (idx >= N_NODES) return;
    int o = g_off[idx] + g_boff[blockIdx.x];
    g_off[idx] = o;
    g_cur[idx] = o;
}

__global__ void scatter_kernel(const int* __restrict__ src, const int* __restrict__ dst) {
    int e = blockIdx.x * blockDim.x + threadIdx.x;
    if (e >= N_EDGES) return;
    int p = atomicAdd(&g_cur[dst[e]], 1);
    g_csr[p] = src[e];
}

// ---------------- TF32 tensor-core GEMM, asymmetric precision ---------------
// C[M,256] = A[M,K] @ B[K,256].
// blockIdx.x==0 -> cols [0,128) (gather operand): 1-term rna-tf32, fp16 out.
//   (error attenuated ~1/sqrt(deg) by the downstream neighbor mean)
// blockIdx.x==1 -> cols [128,256) (root term): 2-term split, fp32 out.

__device__ __forceinline__ void cp_async16(void* smem_dst, const void* gmem_src) {
    uint32_t s = (uint32_t)__cvta_generic_to_shared(smem_dst);
    asm volatile("cp.async.cg.shared.global [%0], [%1], 16;\n" :: "r"(s), "l"(gmem_src));
}

__device__ __forceinline__ uint32_t f2tf32(float x) {
    uint32_t r;
    asm("cvt.rna.tf32.f32 %0, %1;\n" : "=r"(r) : "f"(x));
    return r;
}

__device__ __forceinline__ void split_tf32(float v, uint32_t& hi, uint32_t& lo) {
    hi = f2tf32(v);
    lo = f2tf32(v - __uint_as_float(hi));
}

__device__ __forceinline__ void mma_tf32_16x8x8(
    float& c0, float& c1, float& c2, float& c3,
    uint32_t a0, uint32_t a1, uint32_t a2, uint32_t a3,
    uint32_t b0, uint32_t b1)
{
    asm volatile(
        "mma.sync.aligned.m16n8k8.row.col.f32.tf32.tf32.f32 "
        "{%0,%1,%2,%3}, {%4,%5,%6,%7}, {%8,%9}, {%0,%1,%2,%3};\n"
        : "+f"(c0), "+f"(c1), "+f"(c2), "+f"(c3)
        : "r"(a0), "r"(a1), "r"(a2), "r"(a3), "r"(b0), "r"(b1));
}

#define AS_STRIDE 20
#define BS_STRIDE 136

__global__ __launch_bounds__(256) void gemm1_tf32_kernel(
    const float* __restrict__ A, const float* __restrict__ B,
    __half* __restrict__ Cl, float* __restrict__ Cr, int M, int K)
{
    const int N = 256;
    __shared__ float As[2][128][AS_STRIDE];
    __shared__ float Bs[2][16][BS_STRIDE];

    const int tid  = threadIdx.x;
    const int warp = tid >> 5;
    const int lane = tid & 31;
    const int g    = lane >> 2;
    const int t    = lane & 3;

    const int rowBase = blockIdx.y * 128;
    const int colBase = blockIdx.x * 128;
    const bool twoTerm = (colBase != 0);   // r-half needs the hi/lo split
    const int mBase = (warp >> 2) * 64;
    const int nBase = (warp & 3) * 32;

    float acc[4][4][4];
    #pragma unroll
    for (int i = 0; i < 4; i++)
        #pragma unroll
        for (int j = 0; j < 4; j++)
            #pragma unroll
            for (int c = 0; c < 4; c++) acc[i][j][c] = 0.0f;

    const int nTiles = K >> 4;

    const int am0 = (tid + 0)   >> 2, aq0 = (tid + 0)   & 3;
    const int am1 = (tid + 256) >> 2, aq1 = (tid + 256) & 3;
    const int bk0 = (tid + 0)   >> 5, bq0 = (tid + 0)   & 31;
    const int bk1 = (tid + 256) >> 5, bq1 = (tid + 256) & 31;

    auto issue_tile = [&](int tIdx, int buf) {
        int k0 = tIdx << 4;
        int ga0 = rowBase + am0;
        int ga1 = rowBase + am1;
        if (ga0 < M) cp_async16(&As[buf][am0][aq0 * 4], A + (size_t)ga0 * K + k0 + aq0 * 4);
        if (ga1 < M) cp_async16(&As[buf][am1][aq1 * 4], A + (size_t)ga1 * K + k0 + aq1 * 4);
        cp_async16(&Bs[buf][bk0][bq0 * 4], B + (size_t)(k0 + bk0) * N + colBase + bq0 * 4);
        cp_async16(&Bs[buf][bk1][bq1 * 4], B + (size_t)(k0 + bk1) * N + colBase + bq1 * 4);
        asm volatile("cp.async.commit_group;\n");
    };

    issue_tile(0, 0);

    for (int tIdx = 0; tIdx < nTiles; tIdx++) {
        int buf = tIdx & 1;
        bool hasNext = (tIdx + 1) < nTiles;
        if (hasNext) issue_tile(tIdx + 1, buf ^ 1);
        if (hasNext) asm volatile("cp.async.wait_group 1;\n");
        else         asm volatile("cp.async.wait_group 0;\n");
        __syncthreads();

        #pragma unroll
        for (int ks = 0; ks < 16; ks += 8) {
            uint32_t ah[4][4], al[4][4];
            #pragma unroll
            for (int mi = 0; mi < 4; mi++) {
                int r = mBase + mi * 16 + g;
                if (twoTerm) {
                    split_tf32(As[buf][r    ][ks + t    ], ah[mi][0], al[mi][0]);
                    split_tf32(As[buf][r + 8][ks + t    ], ah[mi][1], al[mi][1]);
                    split_tf32(As[buf][r    ][ks + t + 4], ah[mi][2], al[mi][2]);
                    split_tf32(As[buf][r + 8][ks + t + 4], ah[mi][3], al[mi][3]);
                } else {
                    ah[mi][0] = f2tf32(As[buf][r    ][ks + t    ]);
                    ah[mi][1] = f2tf32(As[buf][r + 8][ks + t    ]);
                    ah[mi][2] = f2tf32(As[buf][r    ][ks + t + 4]);
                    ah[mi][3] = f2tf32(As[buf][r + 8][ks + t + 4]);
                }
            }
            uint32_t bh[4][2];
            #pragma unroll
            for (int ni = 0; ni < 4; ni++) {
                int c = nBase + ni * 8 + g;
                bh[ni][0] = f2tf32(Bs[buf][ks + t    ][c]);
                bh[ni][1] = f2tf32(Bs[buf][ks + t + 4][c]);
            }
            #pragma unroll
            for (int mi = 0; mi < 4; mi++)
                #pragma unroll
                for (int ni = 0; ni < 4; ni++) {
                    if (twoTerm)
                        mma_tf32_16x8x8(acc[mi][ni][0], acc[mi][ni][1],
                                        acc[mi][ni][2], acc[mi][ni][3],
                                        al[mi][0], al[mi][1], al[mi][2], al[mi][3],
                                        bh[ni][0], bh[ni][1]);
                    mma_tf32_16x8x8(acc[mi][ni][0], acc[mi][ni][1],
                                    acc[mi][ni][2], acc[mi][ni][3],
                                    ah[mi][0], ah[mi][1], ah[mi][2], ah[mi][3],
                                    bh[ni][0], bh[ni][1]);
                }
        }
        __syncthreads();
    }

    // split epilogue
    #pragma unroll
    for (int mi = 0; mi < 4; mi++) {
        int r0 = rowBase + mBase + mi * 16 + g;
        int r1 = r0 + 8;
        #pragma unroll
        for (int ni = 0; ni < 4; ni++) {
            int c = colBase + nBase + ni * 8 + 2 * t;
            if (colBase == 0) {
                if (r0 < M) {
                    __half2 v = __floats2half2_rn(acc[mi][ni][0], acc[mi][ni][1]);
                    *(__half2*)(Cl + (size_t)r0 * HID + c) = v;
                }
                if (r1 < M) {
                    __half2 v = __floats2half2_rn(acc[mi][ni][2], acc[mi][ni][3]);
                    *(__half2*)(Cl + (size_t)r1 * HID + c) = v;
                }
            } else {
                int cr = c - 128;
                if (r0 < M) {
                    float2 v = make_float2(acc[mi][ni][0], acc[mi][ni][1]);
                    *(float2*)(Cr + (size_t)r0 * HID + cr) = v;
                }
                if (r1 < M) {
                    float2 v = make_float2(acc[mi][ni][2], acc[mi][ni][3]);
                    *(float2*)(Cr + (size_t)r1 * HID + cr) = v;
                }
            }
        }
    }
}

// ---------------- aggregation: warp per node, fp16 gather -------------------
__device__ __forceinline__ void acc_half4(float4& a, uint2 raw) {
    __half2 h0 = *reinterpret_cast<__half2*>(&raw.x);
    __half2 h1 = *reinterpret_cast<__half2*>(&raw.y);
    float2 f0 = __half22float2(h0);
    float2 f1 = __half22float2(h1);
    a.x += f0.x; a.y += f0.y; a.z += f1.x; a.w += f1.y;
}

// layer 1: h1 = relu( mean_j tl[j] + b_l1 + tr[i] ); write fp32 + fp16 copies
__global__ __launch_bounds__(256) void agg1_kernel(const float* __restrict__ b_l1) {
    int node = (blockIdx.x * blockDim.x + threadIdx.x) >> 5;
    int lane = threadIdx.x & 31;
    if (node >= N_NODES) return;
    int s = g_off[node], e = g_off[node + 1];
    float4 a0 = make_float4(0.f, 0.f, 0.f, 0.f);
    float4 a1 = make_float4(0.f, 0.f, 0.f, 0.f);
    int i = s;
    for (; i + 7 < e; i += 8) {
        int sj[8];
        #pragma unroll
        for (int u = 0; u < 8; u++) sj[u] = g_csr[i + u];
        uint2 v[8];
        #pragma unroll
        for (int u = 0; u < 8; u++)
            v[u] = *(const uint2*)(g_tlh + (size_t)sj[u] * HID + lane * 4);
        #pragma unroll
        for (int u = 0; u < 4; u++) acc_half4(a0, v[u]);
        #pragma unroll
        for (int u = 4; u < 8; u++) acc_half4(a1, v[u]);
    }
    for (; i < e; i++) {
        int s0 = g_csr[i];
        uint2 v0 = *(const uint2*)(g_tlh + (size_t)s0 * HID + lane * 4);
        acc_half4(a0, v0);
    }
    float inv = 1.0f / fmaxf((float)(e - s), 1.0f);
    float4 r  = *(const float4*)(g_tr + (size_t)node * HID + lane * 4);
    float4 bb = *(const float4*)(b_l1 + lane * 4);
    float4 o;
    o.x = fmaxf((a0.x + a1.x) * inv + bb.x + r.x, 0.f);
    o.y = fmaxf((a0.y + a1.y) * inv + bb.y + r.y, 0.f);
    o.z = fmaxf((a0.z + a1.z) * inv + bb.z + r.z, 0.f);
    o.w = fmaxf((a0.w + a1.w) * inv + bb.w + r.w, 0.f);
    *(float4*)(g_h1 + (size_t)node * HID + lane * 4) = o;
    uint2 packed;
    __half2 p0 = __floats2half2_rn(o.x, o.y);
    __half2 p1 = __floats2half2_rn(o.z, o.w);
    packed.x = *reinterpret_cast<uint32_t*>(&p0);
    packed.y = *reinterpret_cast<uint32_t*>(&p1);
    *(uint2*)(g_h1h + (size_t)node * HID + lane * 4) = packed;
}

// layer 2 aggregation FUSED with folded decoder (fp16 gather, fp32 own)
__global__ __launch_bounds__(256) void agg2_sab_kernel() {
    int node = (blockIdx.x * blockDim.x + threadIdx.x) >> 5;
    int lane = threadIdx.x & 31;
    if (node >= N_NODES) return;
    int s = g_off[node], e = g_off[node + 1];
    float4 a0 = make_float4(0.f, 0.f, 0.f, 0.f);
    float4 a1 = make_float4(0.f, 0.f, 0.f, 0.f);
    int i = s;
    for (; i + 7 < e; i += 8) {
        int sj[8];
        #pragma unroll
        for (int u = 0; u < 8; u++) sj[u] = g_csr[i + u];
        uint2 v[8];
        #pragma unroll
        for (int u = 0; u < 8; u++)
            v[u] = *(const uint2*)(g_h1h + (size_t)sj[u] * HID + lane * 4);
        #pragma unroll
        for (int u = 0; u < 4; u++) acc_half4(a0, v[u]);
        #pragma unroll
        for (int u = 4; u < 8; u++) acc_half4(a1, v[u]);
    }
    for (; i < e; i++) {
        int s0 = g_csr[i];
        uint2 v0 = *(const uint2*)(g_h1h + (size_t)s0 * HID + lane * 4);
        acc_half4(a0, v0);
    }
    float inv = 1.0f / fmaxf((float)(e - s), 1.0f);
    float4 m;
    m.x = (a0.x + a1.x) * inv;
    m.y = (a0.y + a1.y) * inv;
    m.z = (a0.z + a1.z) * inv;
    m.w = (a0.w + a1.w) * inv;
    float4 o = *(const float4*)(g_h1 + (size_t)node * HID + lane * 4);

    float4 wa0 = *(const float4*)(g_w2a + lane * 4);
    float4 wa1 = *(const float4*)(g_w2a + 128 + lane * 4);
    float4 wb0 = *(const float4*)(g_w2b + lane * 4);
    float4 wb1 = *(const float4*)(g_w2b + 128 + lane * 4);

    float da = m.x * wa0.x + m.y * wa0.y + m.z * wa0.z + m.w * wa0.w
             + o.x * wa1.x + o.y * wa1.y + o.z * wa1.z + o.w * wa1.w;
    float db = m.x * wb0.x + m.y * wb0.y + m.z * wb0.z + m.w * wb0.w
             + o.x * wb1.x + o.y * wb1.y + o.z * wb1.z + o.w * wb1.w;
    #pragma unroll
    for (int off = 16; off > 0; off >>= 1) {
        da += __shfl_xor_sync(0xffffffff, da, off);
        db += __shfl_xor_sync(0xffffffff, db, off);
    }
    if (lane == 0) {
        g_sa[node] = da + g_c[0];
        g_sb[node] = db + g_c[1];
    }
}

__global__ void score_kernel(const int* __restrict__ pos, const int* __restrict__ neg,
                             const float* __restrict__ b_lin, float* __restrict__ out)
{
    int idx = blockIdx.x * blockDim.x + threadIdx.x;
    if (idx >= 1000000) return;
    float b = b_lin[0];
    if (idx < 500000) {
        int s = pos[idx];
        int d = pos[500000 + idx];
        out[idx] = g_sa[s] + g_sb[d] + b;
    } else {
        int e = idx - 500000;
        int s = neg[e];
        int d = neg[500000 + e];
        out[idx] = g_sa[s] + g_sb[d] + b;
    }
}

// ---------------- launch ----------------------------------------------------
extern "C" void kernel_launch(void* const* d_in, const int* in_sizes, int n_in,
                              void* d_out, int out_size)
{
    const float* x     = (const float*)d_in[0];
    const int*   ei    = (const int*)  d_in[1];
    const int*   pos   = (const int*)  d_in[2];
    const int*   neg   = (const int*)  d_in[3];
    const float* W_l1  = (const float*)d_in[4];
    const float* b_l1  = (const float*)d_in[5];
    const float* W_r1  = (const float*)d_in[6];
    const float* W_l2  = (const float*)d_in[7];
    const float* b_l2  = (const float*)d_in[8];
    const float* W_r2  = (const float*)d_in[9];
    const float* W_lin = (const float*)d_in[10];
    const float* b_lin = (const float*)d_in[11];
    float*       out   = (float*)d_out;

    const int* e_src = ei;
    const int* e_dst = ei + N_EDGES;

    void *p_tlh, *p_tr, *p_W1;
    cudaGetSymbolAddress(&p_tlh, g_tlh);
    cudaGetSymbolAddress(&p_tr,  g_tr);
    cudaGetSymbolAddress(&p_W1,  g_W1);

    // CSR build
    zero_cnt_kernel<<<(N_NODES + 255) / 256, 256>>>();
    hist_kernel<<<(N_EDGES + 255) / 256, 256>>>(e_dst);
    scan_local_kernel<<<NB_SCAN, 256>>>();
    scan_bsum_kernel<<<1, 512>>>();
    scan_add_kernel<<<NB_SCAN, 256>>>();
    scatter_kernel<<<(N_EDGES + 255) / 256, 256>>>(e_src, e_dst);

    // weight prep
    pack_w1_kernel<<<(IN_DIM * 256 + 255) / 256, 256>>>(W_l1, W_r1);
    decoder_pre_kernel<<<1, 256>>>(W_l2, W_r2, b_l2, W_lin);

    // layer 1 GEMM: tl (fp16, 1-term) | tr (fp32, 2-term) = x @ [W_l1 | W_r1]
    {
        dim3 grid(2, (N_NODES + 127) / 128);
        gemm1_tf32_kernel<<<grid, 256>>>(x, (const float*)p_W1,
                                         (__half*)p_tlh, (float*)p_tr,
                                         N_NODES, IN_DIM);
    }
    // h1 = relu(mean-aggregate + b + root)
    agg1_kernel<<<(N_NODES * 32 + 255) / 256, 256>>>(b_l1);

    // layer 2 + decoder fused
    agg2_sab_kernel<<<(N_NODES * 32 + 255) / 256, 256>>>();

    // final scoring
    score_kernel<<<(1000000 + 255) / 256, 256>>>(pos, neg, b_lin, out);
}